// round 15
// baseline (speedup 1.0000x reference)
#include <cuda_runtime.h>
#include <cuda.h>
#include <cuda_fp16.h>
#include <math.h>
#include <stdint.h>

#define S_  512
#define Bb  32
#define Hh  512
#define Dd  512
#define Mrows (S_*Bb)          /* 16384 */
#define NCOLS 4096             /* 7 gates * 512 + 512 fi columns */
#define KTOT 2048

#if defined(__CUDA_ARCH_FEAT_SM103_ALL) || defined(__CUDA_ARCH_SPECIFIC__)
#define TC_PATH 1
#else
#define TC_PATH 0
#endif

static __device__ __half g_PRE[(size_t)Mrows * NCOLS];  // 128 MB (b-major rows: b*512+s)
static __device__ __half g_HW[(size_t)Mrows * Hh];      // masked h0[:-1], fp16 (s-major)
static __device__ __half g_SQ[(size_t)Mrows * Hh];      // seqs, fp16 (s-major)
static __device__ __half g_WB[(size_t)NCOLS * KTOT];    // packed fp16 weights [n][k]
static __device__ float g_HHATP[8 * Bb * Hh];
static __device__ float g_FG[Bb*Hh];
static __device__ float g_OG[Bb*Hh];
static __device__ float g_GW1[Bb*Hh];
static __device__ float g_VV[7*Bb*Hh];
static __device__ float g_GPl[64*Bb*Hh];
static __device__ float g_GPc[64*Bb*Hh];

__device__ __forceinline__ float sigf(float x){ return 1.0f/(1.0f + __expf(-x)); }

__device__ __forceinline__ uint32_t smem_u32(const void* p){
    uint32_t a;
    asm("{ .reg .u64 t; cvta.to.shared.u64 t, %1; cvt.u32.u64 %0, t; }"
        : "=r"(a) : "l"(p));
    return a;
}
__device__ __forceinline__ uint2 pack4h(float4 v){
    __half2 a = __floats2half2_rn(v.x, v.y);
    __half2 b = __floats2half2_rn(v.z, v.w);
    uint2 u;
    u.x = *(uint32_t*)&a;
    u.y = *(uint32_t*)&b;
    return u;
}
__device__ __forceinline__ float4 ld4h(const __half* p){
    __half2 a = *(const __half2*)p;
    __half2 b = *(const __half2*)(p + 2);
    return make_float4(__low2float(a), __high2float(a),
                       __low2float(b), __high2float(b));
}

#if TC_PATH
__device__ __forceinline__ uint32_t elect_one(){
    uint32_t p;
    asm volatile("{ .reg .pred P; elect.sync _|P, 0xFFFFFFFF; selp.b32 %0, 1, 0, P; }"
                 : "=r"(p));
    return p;
}
__device__ __forceinline__ void mbar_init(uint32_t a, uint32_t cnt){
    asm volatile("mbarrier.init.shared.b64 [%0], %1;" :: "r"(a), "r"(cnt) : "memory");
}
__device__ __forceinline__ void mbar_expect_tx(uint32_t a, uint32_t bytes){
    asm volatile("mbarrier.arrive.expect_tx.shared.b64 _, [%0], %1;"
                 :: "r"(a), "r"(bytes) : "memory");
}
__device__ __forceinline__ void mbar_wait(uint32_t a, uint32_t parity){
    asm volatile(
        "{\n\t.reg .pred P;\n\t"
        "WL_%=:\n\t"
        "mbarrier.try_wait.parity.acquire.cta.shared::cta.b64 P, [%0], %1;\n\t"
        "@P bra WD_%=;\n\t"
        "bra WL_%=;\n\t"
        "WD_%=:\n\t}"
        :: "r"(a), "r"(parity) : "memory");
}
__device__ __forceinline__ void tma_ld3(uint32_t smem, const void* map,
                                        int32_t x, int32_t y, int32_t z, uint32_t mbar){
    asm volatile(
        "cp.async.bulk.tensor.3d.shared::cta.global.tile.mbarrier::complete_tx::bytes "
        "[%0], [%1, {%2, %3, %4}], [%5];"
        :: "r"(smem), "l"(map), "r"(x), "r"(y), "r"(z), "r"(mbar) : "memory");
}
__device__ __forceinline__ void tmem_alloc(uint32_t dst_smem, uint32_t ncols){
    asm volatile("tcgen05.alloc.cta_group::1.sync.aligned.shared::cta.b32 [%0], %1;"
                 :: "r"(dst_smem), "r"(ncols) : "memory");
}
__device__ __forceinline__ void tmem_relinquish(){
    asm volatile("tcgen05.relinquish_alloc_permit.cta_group::1.sync.aligned;");
}
__device__ __forceinline__ void tmem_dealloc(uint32_t tmem, uint32_t ncols){
    asm volatile("tcgen05.dealloc.cta_group::1.sync.aligned.b32 %0, %1;"
                 :: "r"(tmem), "r"(ncols));
}
__device__ __forceinline__ void mma_f16(uint32_t d, uint64_t ad, uint64_t bd,
                                        uint32_t idesc, uint32_t en){
    asm volatile(
        "{\n\t.reg .pred p;\n\t"
        "setp.ne.u32 p, %4, 0;\n\t"
        "tcgen05.mma.cta_group::1.kind::f16 [%0], %1, %2, %3, p;\n\t}"
        :: "r"(d), "l"(ad), "l"(bd), "r"(idesc), "r"(en) : "memory");
}
__device__ __forceinline__ void mma_commit(uint32_t mbar){
    asm volatile("tcgen05.commit.cta_group::1.mbarrier::arrive::one.shared::cluster.b64 [%0];"
                 :: "r"(mbar) : "memory");
}
__device__ __forceinline__ void tc_fence_after(){
    asm volatile("tcgen05.fence::after_thread_sync;" ::: "memory");
}
__device__ __forceinline__ void tc_fence_before(){
    asm volatile("tcgen05.fence::before_thread_sync;" ::: "memory");
}
__device__ __forceinline__ void tmem_wait_ld(){
    asm volatile("tcgen05.wait::ld.sync.aligned;" ::: "memory");
}
__device__ __forceinline__ void tmem_ld32(uint32_t* r, uint32_t addr){
    asm volatile(
        "tcgen05.ld.sync.aligned.32x32b.x32.b32 "
        "{%0, %1, %2, %3, %4, %5, %6, %7, "
        " %8, %9, %10, %11, %12, %13, %14, %15, "
        " %16, %17, %18, %19, %20, %21, %22, %23, "
        " %24, %25, %26, %27, %28, %29, %30, %31}, [%32];"
        : "=r"(r[0]),  "=r"(r[1]),  "=r"(r[2]),  "=r"(r[3]),
          "=r"(r[4]),  "=r"(r[5]),  "=r"(r[6]),  "=r"(r[7]),
          "=r"(r[8]),  "=r"(r[9]),  "=r"(r[10]), "=r"(r[11]),
          "=r"(r[12]), "=r"(r[13]), "=r"(r[14]), "=r"(r[15]),
          "=r"(r[16]), "=r"(r[17]), "=r"(r[18]), "=r"(r[19]),
          "=r"(r[20]), "=r"(r[21]), "=r"(r[22]), "=r"(r[23]),
          "=r"(r[24]), "=r"(r[25]), "=r"(r[26]), "=r"(r[27]),
          "=r"(r[28]), "=r"(r[29]), "=r"(r[30]), "=r"(r[31])
        : "r"(addr));
}
static constexpr uint64_t DESC_BASE =
    (2ull << 61) | (1ull << 46) | (64ull << 32) | (1ull << 16);
#define IDESC_F16 ((1u<<4)|((128u/8u)<<17)|((128u/16u)<<24))
#endif  // TC_PATH

#define NSTAGE 2
#define STAGE_BYTES 49152            /* A 16KB + B 32KB (fp16, K=64) */
#define SMEM_TOTAL (1024 + NSTAGE*STAGE_BYTES)   /* 99328 -> 2 CTAs/SM */

// ------------------------------------------------------------------
// k_fused: block-range dispatch of four independent prep jobs.
//   [0, 8192)       : masked fp16 copy h0->g_HW ; seqs->g_SQ (8 floats/thr)
//   [8192, 12288)   : packed fp16 weight matrix g_WB
//   [12288, 12800)  : h_hat partial sums (from h0 + mask, fp32)
//   [12800, 13312)  : GEMV targets 2..9 (gw1, VV[0..6]) — input-only deps
// ------------------------------------------------------------------
__global__ void __launch_bounds__(256)
k_fused(const float* __restrict__ h0, const float* __restrict__ seqs,
        const float* __restrict__ Ww, const float* __restrict__ Wu,
        const float* __restrict__ Su, const float* __restrict__ Sw,
        const float* __restrict__ Sb, const float* __restrict__ Wv,
        const float* __restrict__ Wb, const int* __restrict__ seq_lens)
{
    const int bid = blockIdx.x;
    const int tid = threadIdx.x;
    __shared__ float sx1[4][512];

    if (bid < 8192){
        size_t idx = (size_t)bid * 256 + tid;        // 8-float unit
        const size_t NU = (size_t)Mrows * Hh / 8;    // 1M units per array
        if (idx < NU){
            size_t e = idx << 3;
            int r = (int)(e >> 9);
            int b = r & 31;
            int s = r >> 5;
            float4 v0 = make_float4(0.f,0.f,0.f,0.f);
            float4 v1 = make_float4(0.f,0.f,0.f,0.f);
            if (s < seq_lens[b]){
                v0 = *(const float4*)(h0 + e);
                v1 = *(const float4*)(h0 + e + 4);
            }
            *(uint2*)(g_HW + e)     = pack4h(v0);
            *(uint2*)(g_HW + e + 4) = pack4h(v1);
        } else {
            size_t e = (idx - NU) << 3;
            float4 v0 = *(const float4*)(seqs + e);
            float4 v1 = *(const float4*)(seqs + e + 4);
            *(uint2*)(g_SQ + e)     = pack4h(v0);
            *(uint2*)(g_SQ + e + 4) = pack4h(v1);
        }
    } else if (bid < 12288){
        int n = bid - 8192;
        __half* dst = g_WB + (size_t)n * KTOT;
        #pragma unroll
        for (int half = 0; half < 2; ++half){
            int k4 = tid*4 + half*1024;
            float4 v;
            if (n < 3584){
                int g = n >> 9, h = n & 511;
                int seg = k4 >> 9, kk = k4 & 511;
                const float* src = (seg < 3)
                    ? (Ww + ((size_t)(g*512 + h))*1536 + seg*512 + kk)
                    : (Wu + ((size_t)(g*512 + h))*512 + kk);
                v = *(const float4*)src;
            } else {
                int h = n - 3584;
                if (k4 < 512) v = *(const float4*)(Su + ((size_t)(512 + h))*512 + k4);
                else          v = make_float4(0.f,0.f,0.f,0.f);
            }
            *(uint2*)(dst + k4) = pack4h(v);
        }
    } else if (bid < 12800){
        int idx = bid - 12288;       // 0..511
        int b    = idx & 31;
        int sc   = (idx >> 5) & 7;
        int half = idx >> 8;
        int h = half*256 + tid;
        int len = seq_lens[b];
        int s1 = sc*64;
        int s2 = min(s1 + 64, len);
        const float* p = h0 + ((size_t)s1*32 + b)*512 + h;
        float acc = 0.f;
        for (int s = s1; s < s2; ++s){
            acc += *p;
            p += 16384;
        }
        g_HHATP[(size_t)sc*16384 + b*512 + h] = acc;
    } else {
        // GEMV targets 2..9: 8 targets x 64 blocks each
        int idx = bid - 12800;           // 0..511
        const int target = 2 + (idx >> 6);
        int rest = idx & 63;
        const int bg = (rest >> 3) << 2; // 8 b-groups of 4
        const int hz = (rest & 7) << 6;  // 8 h-groups of 64

        for (int i = tid; i < 4*512; i += 256){
            int bb = i >> 9, k = i & 511;
            int b = bg + bb;
            sx1[bb][k] = h0[((size_t)(S_*Bb) + b)*Hh + k];
        }
        __syncthreads();

        const int warp = tid >> 5, lane = tid & 31;
        const int hh = hz + warp*8;

        float acc[4][8];
        #pragma unroll
        for (int bb=0;bb<4;bb++)
            #pragma unroll
            for (int j=0;j<8;j++) acc[bb][j] = 0.f;

        const float* wb1 = (target == 2)
            ? (Sw + ((size_t)(512 + hh))*512)
            : (Wv + ((size_t)((target-3)*512 + hh))*512);

        #pragma unroll 4
        for (int i = 0; i < 16; ++i){
            int k = lane + (i << 5);
            float w[8];
            #pragma unroll
            for (int j=0;j<8;j++) w[j] = wb1[(size_t)j*512 + k];
            #pragma unroll
            for (int bb=0;bb<4;bb++){
                float a = sx1[bb][k];
                #pragma unroll
                for (int j=0;j<8;j++) acc[bb][j] += a * w[j];
            }
        }

        #pragma unroll
        for (int bb=0;bb<4;bb++)
            #pragma unroll
            for (int j=0;j<8;j++){
                float v = acc[bb][j];
                #pragma unroll
                for (int o=16;o;o>>=1) v += __shfl_xor_sync(0xffffffffu, v, o);
                acc[bb][j] = v;
            }

        if (lane == 0){
            #pragma unroll
            for (int bb=0;bb<4;bb++){
                int b = bg + bb;
                #pragma unroll
                for (int j=0;j<8;j++){
                    int h = hh + j;
                    float v = acc[bb][j];
                    if (target == 2) g_GW1[b*512 + h] = v + Sb[512 + h];
                    else {
                        int g = target - 3;
                        g_VV[((size_t)g*Bb + b)*Hh + h] = v + Wb[g*512 + h];
                    }
                }
            }
        }
    }
}

// ------------------------------------------------------------------
// main GEMM (fp16 operands, fp32 accum). Tile M=128 x N=256.
// K-chunk = 64 fp16 (128B rows). grid(16,136), 2 CTAs/SM.
//   mb < 128 : GEMM tiles (R8-proven path)
//   mb >= 128: fg/og GEMV CTAs (fold of old k_small01; tail-scheduled)
// ------------------------------------------------------------------
__global__ void __launch_bounds__(256, 2)
k_gemm(const __grid_constant__ CUtensorMap mapHW,
       const __grid_constant__ CUtensorMap mapSQ,
       const __grid_constant__ CUtensorMap mapWB,
       const int* __restrict__ seq_lens,
       const float* __restrict__ h0,
       const float* __restrict__ Sw, const float* __restrict__ Su,
       const float* __restrict__ Sb)
{
    extern __shared__ char smem_raw[];
    const int tid = threadIdx.x;
    const int nb = blockIdx.x;     // 0..15
    const int mb = blockIdx.y;     // 0..135

    if (mb >= 128){
        // ---------------- fg/og GEMV (uses dynamic smem) ----------------
        int idx2 = (mb - 128)*16 + nb;     // 0..127
        const int target = idx2 >> 6;      // 0=fg, 1=og
        int rest = idx2 & 63;
        const int bg = (rest >> 3) << 2;
        const int hz = (rest & 7) << 6;
        float* sx1 = (float*)smem_raw;          // 4x512
        float* sx2 = sx1 + 4*512;               // 4x512

        for (int i = tid; i < 4*512; i += 256){
            int bb = i >> 9, k = i & 511;
            int b = bg + bb;
            sx1[bb*512 + k] = h0[((size_t)(S_*Bb) + b)*Hh + k];
            float s8 = 0.f;
            #pragma unroll
            for (int sc = 0; sc < 8; ++sc)
                s8 += g_HHATP[(size_t)sc*16384 + b*512 + k];
            sx2[bb*512 + k] = s8 * (1.0f/512.0f);
        }
        __syncthreads();

        const int warp = tid >> 5, lane = tid & 31;
        const int hh = hz + warp*8;
        const int si = (target==0) ? 0 : 2;

        float acc[4][8];
        #pragma unroll
        for (int bb=0;bb<4;bb++)
            #pragma unroll
            for (int j=0;j<8;j++) acc[bb][j] = 0.f;

        const float* wb1 = Sw + ((size_t)(si*512 + hh))*512;
        const float* wb2 = Su + ((size_t)(si*512 + hh))*512;

        #pragma unroll 4
        for (int i = 0; i < 16; ++i){
            int k = lane + (i << 5);
            float w1[8], w2[8];
            #pragma unroll
            for (int j=0;j<8;j++){ w1[j] = wb1[(size_t)j*512 + k]; w2[j] = wb2[(size_t)j*512 + k]; }
            #pragma unroll
            for (int bb=0;bb<4;bb++){
                float a1 = sx1[bb*512 + k];
                float a2 = sx2[bb*512 + k];
                #pragma unroll
                for (int j=0;j<8;j++) acc[bb][j] += a1*w1[j] + a2*w2[j];
            }
        }

        #pragma unroll
        for (int bb=0;bb<4;bb++)
            #pragma unroll
            for (int j=0;j<8;j++){
                float v = acc[bb][j];
                #pragma unroll
                for (int o=16;o;o>>=1) v += __shfl_xor_sync(0xffffffffu, v, o);
                acc[bb][j] = v;
            }

        if (lane == 0){
            #pragma unroll
            for (int bb=0;bb<4;bb++){
                int b = bg + bb;
                #pragma unroll
                for (int j=0;j<8;j++){
                    int h = hh + j;
                    float v = sigf(acc[bb][j] + Sb[si*512 + h]);
                    (target==0 ? g_FG : g_OG)[b*512 + h] = v;
                }
            }
        }
        return;
    }

    const int b  = mb >> 2;
    const int s0 = (mb & 3) << 7;
    if (s0 >= seq_lens[b]) return;

    const bool isFi = (nb >= 14);
    const int NC = isFi ? 8 : 32;

#if TC_PATH
    char* sbp = (char*)(((uintptr_t)smem_raw + 1023) & ~(uintptr_t)1023);
    const uint32_t sbu = smem_u32(sbp);
    const int warp = tid >> 5;

    if (tid == 0){
        #pragma unroll
        for (int s = 0; s < NSTAGE; ++s){
            mbar_init(sbu + 16 + 8*s, 1);     // full
            mbar_init(sbu + 48 + 8*s, 1);     // done
        }
        mbar_init(sbu + 80, 1);               // final
    }
    if (warp == 0){ tmem_alloc(sbu, 256); tmem_relinquish(); }
    __syncthreads();
    uint32_t tmem;
    asm volatile("ld.shared.b32 %0, [%1];" : "=r"(tmem) : "r"(sbu));

    if (warp == 0){
        if (elect_one()){
            for (int c = 0; c < NC; ++c){
                const int st = c % NSTAGE;
                const int q  = c / NSTAGE;
                if (c >= NSTAGE) mbar_wait(sbu + 48 + 8*st, (q - 1) & 1);
                const uint32_t full = sbu + 16 + 8*st;
                mbar_expect_tx(full, STAGE_BYTES);
                const uint32_t aAddr = sbu + 1024 + st*STAGE_BYTES;
                const uint32_t bAddr = aAddr + 16384;
                if (isFi){
                    tma_ld3(aAddr, &mapHW, c*64, b, s0, full);
                } else {
                    const int seg = c >> 3;
                    const int kc  = (c & 7) << 6;
                    if (seg < 3) tma_ld3(aAddr, &mapHW, kc, b, s0 + seg - 1, full);
                    else         tma_ld3(aAddr, &mapSQ, kc, b, s0, full);
                }
                tma_ld3(bAddr, &mapWB, c*64, nb*256, 0, full);
            }
        }
    } else if (warp == 1){
        if (elect_one()){
            for (int c = 0; c < NC; ++c){
                const int st = c % NSTAGE;
                const int q  = c / NSTAGE;
                mbar_wait(sbu + 16 + 8*st, q & 1);
                const uint32_t aAddr = sbu + 1024 + st*STAGE_BYTES;
                const uint32_t bAddr = aAddr + 16384;
                uint64_t ad  = DESC_BASE | ((aAddr >> 4) & 0x3FFFu);
                uint64_t bd0 = DESC_BASE | ((bAddr >> 4) & 0x3FFFu);
                uint64_t bd1 = bd0 + 1024;
                #pragma unroll
                for (int ks = 0; ks < 4; ++ks){
                    uint32_t en = (c > 0 || ks > 0) ? 1u : 0u;
                    mma_f16(tmem,       ad + 2*ks, bd0 + 2*ks, IDESC_F16, en);
                    mma_f16(tmem + 128, ad + 2*ks, bd1 + 2*ks, IDESC_F16, en);
                }
                mma_commit(sbu + 48 + 8*st);
            }
            mma_commit(sbu + 80);
        }
    }

    mbar_wait(sbu + 80, 0);
    tc_fence_after();

    // epilogue: TMEM f32 -> fp16 PRE
    {
        const int w = tid >> 5, lane = tid & 31;
        const int sub = w & 3;
        const int colh = (w >> 2) * 128;
        const uint32_t tb = tmem + ((uint32_t)sub << 21) + colh;
        __half* dst0 = g_PRE + ((size_t)(b*512 + s0 + sub*32 + lane))*NCOLS + nb*256 + colh;
        #pragma unroll
        for (int qq = 0; qq < 4; ++qq){
            uint32_t r[32];
            tmem_ld32(r, tb + qq*32);
            tmem_wait_ld();
            uint32_t hp[16];
            #pragma unroll
            for (int k = 0; k < 16; ++k){
                __half2 h2 = __floats2half2_rn(__uint_as_float(r[2*k]),
                                               __uint_as_float(r[2*k+1]));
                hp[k] = *(uint32_t*)&h2;
            }
            __half* dst = dst0 + qq*32;
            #pragma unroll
            for (int k = 0; k < 4; ++k)
                *(uint4*)(dst + k*8) = *(const uint4*)(hp + k*4);
        }
    }
    tc_fence_before();
    __syncthreads();
    if (warp == 0) tmem_dealloc(tmem, 256);

#else
    // ================= SIMT fallback (generic pass; not expected to run) =================
    float (*As)[132] = (float (*)[132])smem_raw;
    float (*Bs)[132] = (float (*)[132])(smem_raw + 16*132*4);

    const int arow = tid >> 2;
    const int acol = (tid & 3) << 2;
    const int m1 = arow, m2 = arow + 64;
    const int bcol = tid >> 2;
    const int bkg  = (tid & 3) << 2;
    const int ty8 = (tid >> 4) << 3;
    const int tx8 = (tid & 15) << 3;
    const int Kmax = isFi ? 512 : 2048;

    for (int p = 0; p < 2; ++p){
        const int coln = nb*256 + p*128;
        float acc[8][8];
        #pragma unroll
        for (int i=0;i<8;i++)
            #pragma unroll
            for (int j=0;j<8;j++) acc[i][j]=0.f;

        for (int k0 = 0; k0 < Kmax; k0 += 16){
            const int seg = isFi ? 1 : (k0 >> 9);
            const int kc  = isFi ? k0 : (k0 & 511);
            const int sh  = isFi ? 0 : (seg - 1);

            float4 a1, a2;
            if (!isFi && seg == 3){
                a1 = ld4h(g_SQ + ((size_t)((s0+m1)*32 + b))*512 + kc + acol);
                a2 = ld4h(g_SQ + ((size_t)((s0+m2)*32 + b))*512 + kc + acol);
            } else {
                int sp1 = s0 + m1 + sh, sp2 = s0 + m2 + sh;
                a1 = ((unsigned)sp1 < 512u) ? ld4h(g_HW + ((size_t)(sp1*32 + b))*512 + kc + acol)
                                            : make_float4(0.f,0.f,0.f,0.f);
                a2 = ((unsigned)sp2 < 512u) ? ld4h(g_HW + ((size_t)(sp2*32 + b))*512 + kc + acol)
                                            : make_float4(0.f,0.f,0.f,0.f);
            }
            float4 w1 = ld4h(g_WB + ((size_t)(coln + bcol))*KTOT + k0 + bkg);
            float4 w2 = ld4h(g_WB + ((size_t)(coln + bcol + 64))*KTOT + k0 + bkg);
            __syncthreads();
            As[acol+0][m1] = a1.x; As[acol+1][m1] = a1.y;
            As[acol+2][m1] = a1.z; As[acol+3][m1] = a1.w;
            As[acol+0][m2] = a2.x; As[acol+1][m2] = a2.y;
            As[acol+2][m2] = a2.z; As[acol+3][m2] = a2.w;
            Bs[bkg+0][bcol] = w1.x; Bs[bkg+1][bcol] = w1.y;
            Bs[bkg+2][bcol] = w1.z; Bs[bkg+3][bcol] = w1.w;
            Bs[bkg+0][bcol+64] = w2.x; Bs[bkg+1][bcol+64] = w2.y;
            Bs[bkg+2][bcol+64] = w2.z; Bs[bkg+3][bcol+64] = w2.w;
            __syncthreads();
            #pragma unroll
            for (int kk = 0; kk < 16; ++kk){
                float a[8], bv[8];
                *(float4*)&a[0]  = *(const float4*)&As[kk][ty8];
                *(float4*)&a[4]  = *(const float4*)&As[kk][ty8+4];
                *(float4*)&bv[0] = *(const float4*)&Bs[kk][tx8];
                *(float4*)&bv[4] = *(const float4*)&Bs[kk][tx8+4];
                #pragma unroll
                for (int i=0;i<8;i++)
                    #pragma unroll
                    for (int j=0;j<8;j++)
                        acc[i][j] += a[i]*bv[j];
            }
        }
        #pragma unroll
        for (int i=0;i<8;i++){
            __half* pp = g_PRE + ((size_t)(b*512 + s0 + ty8 + i))*NCOLS + coln + tx8;
            *(uint2*)pp     = pack4h(make_float4(acc[i][0],acc[i][1],acc[i][2],acc[i][3]));
            *(uint2*)(pp+4) = pack4h(make_float4(acc[i][4],acc[i][5],acc[i][6],acc[i][7]));
        }
        __syncthreads();
    }
#endif
}

// ------------------------------------------------------------------
// global cell, stage 1: partial (l, cacc) over 8-s chunks
// ------------------------------------------------------------------
__global__ void kg_part(const float* __restrict__ c0, const int* __restrict__ seq_lens)
{
    int b = blockIdx.x, sc = blockIdx.y, h = threadIdx.x;
    int len = seq_lens[b];
    int s1 = sc*8;
    int s2 = min(s1 + 8, len);
    float g1 = g_GW1[b*512 + h];
    const __half* prep = g_PRE + ((size_t)(b*512 + s1))*NCOLS + 3584 + h;
    const float* cp    = c0 + ((size_t)s1*32 + b)*512 + h;
    float l = 0.f, cacc = 0.f;
    for (int s = s1; s < s2; ++s){
        float e = __expf(sigf(g1 + __half2float(*prep)));
        l += e;
        cacc += e * (*cp);
        prep += NCOLS;
        cp   += 16384;
    }
    g_GPl[(size_t)sc*16384 + b*512 + h] = l;
    g_GPc[(size_t)sc*16384 + b*512 + h] = cacc;
}

// ------------------------------------------------------------------
// global cell, stage 2: reduce + c_g / h_g.
// 256 blocks x 256 threads; 4 quarters of 16 chunks per (b,h),
// coalesced loads (warp lanes = consecutive elements), smem combine.
// ------------------------------------------------------------------
__global__ void __launch_bounds__(256)
kg_fin(const float* __restrict__ c0, float* __restrict__ out)
{
    __shared__ float sl[256], sc_[256];
    const int tid = threadIdx.x;
    const int e = blockIdx.x*64 + (tid & 63);    // element index in [0,16384)
    const int q = tid >> 6;                      // quarter 0..3
    float l = 0.f, cacc = 0.f;
    #pragma unroll
    for (int i = 0; i < 16; ++i){
        int sc = q*16 + i;
        l    += g_GPl[(size_t)sc*16384 + e];
        cacc += g_GPc[(size_t)sc*16384 + e];
    }
    sl[tid] = l; sc_[tid] = cacc;
    __syncthreads();
    if (tid < 64){
        l    = sl[tid]  + sl[tid+64]  + sl[tid+128]  + sl[tid+192];
        cacc = sc_[tid] + sc_[tid+64] + sc_[tid+128] + sc_[tid+192];
        int b = e >> 9;
        int h = e & 511;
        size_t gidx = ((size_t)(S_*Bb) + b)*Hh + h;
        float cg = g_FG[b*512 + h]*c0[gidx] + cacc / l;
        float hg = g_OG[b*512 + h]*tanhf(cg);
        const size_t CT = (size_t)(S_+1)*Bb*Hh;
        out[gidx] = hg;
        out[CT + gidx] = cg;
    }
}

// ------------------------------------------------------------------
// window cell epilogue (4 h per thread: uint2 PRE, float4 c0/VV/out)
// ------------------------------------------------------------------
__global__ void __launch_bounds__(256)
k_epi(const float* __restrict__ c0, const int* __restrict__ seq_lens,
      float* __restrict__ out)
{
    size_t idx = (size_t)blockIdx.x*256 + threadIdx.x;   // 4h unit index
    int h4 = (int)(idx & 127);
    size_t rc = idx >> 7;          // s*32 + b
    int b = (int)(rc & 31);
    int s = (int)(rc >> 5);
    int len = seq_lens[b];
    const size_t CT = (size_t)(S_+1)*Bb*Hh;
    float4* o1 = (float4*)(out + rc*512 + h4*4);
    float4* o2 = (float4*)(out + CT + rc*512 + h4*4);
    if (s >= len){
        *o1 = make_float4(0.f, 0.f, 0.f, 0.f);
        *o2 = make_float4(0.f, 0.f, 0.f, 0.f);
        return;
    }

    const __half* prow = g_PRE + ((size_t)b*512 + s)*NCOLS + h4*4;
    float px[7][4];
    #pragma unroll
    for (int g = 0; g < 7; ++g){
        uint2 raw = *(const uint2*)(prow + g*512);
        __half2 a = *(__half2*)&raw.x;
        __half2 bb2 = *(__half2*)&raw.y;
        float4 vv = *(const float4*)(g_VV + ((size_t)g*Bb + b)*Hh + h4*4);
        px[g][0] = __low2float(a)   + vv.x;
        px[g][1] = __high2float(a)  + vv.y;
        px[g][2] = __low2float(bb2) + vv.z;
        px[g][3] = __high2float(bb2)+ vv.w;
    }

    float4 cl  = (s >= 1) ? *(const float4*)(c0 + (rc-32)*Hh + h4*4) : make_float4(0.f,0.f,0.f,0.f);
    float4 cc  = *(const float4*)(c0 + rc*Hh + h4*4);
    float4 cr  = (s+1 < S_ && s+1 < len) ? *(const float4*)(c0 + (rc+32)*Hh + h4*4)
                                         : make_float4(0.f,0.f,0.f,0.f);
    float4 cg1 = *(const float4*)(c0 + ((size_t)(S_*Bb) + b)*Hh + h4*4);

    float clv[4] = {cl.x, cl.y, cl.z, cl.w};
    float ccv[4] = {cc.x, cc.y, cc.z, cc.w};
    float crv[4] = {cr.x, cr.y, cr.z, cr.w};
    float cgv[4] = {cg1.x, cg1.y, cg1.z, cg1.w};
    float hw[4], cw4[4];
    #pragma unroll
    for (int j = 0; j < 4; ++j){
        float si_ = sigf(px[0][j]);
        float sl_ = sigf(px[1][j]);
        float sr_ = sigf(px[2][j]);
        float sf_ = sigf(px[3][j]);
        float ss_ = sigf(px[4][j]);
        float so_ = sigf(px[5][j]);
        float u_  = tanhf(px[6][j]);

        float e0 = __expf(sl_);
        float e1 = __expf(sf_);
        float e2 = __expf(sr_);
        float e3 = __expf(ss_);
        float e4 = __expf(si_);
        float inv = 1.f/(e0+e1+e2+e3+e4);

        float cw = (e0*clv[j] + e1*ccv[j] + e2*crv[j] + e3*cgv[j] + e4*u_) * inv;
        hw[j] = so_ * tanhf(cw);
        cw4[j] = cw;
    }
    *o1 = make_float4(hw[0], hw[1], hw[2], hw[3]);
    *o2 = make_float4(cw4[0], cw4[1], cw4[2], cw4[3]);
}

// ------------------------------------------------------------------
// host
// ------------------------------------------------------------------
typedef CUresult (*EncFn)(CUtensorMap*, CUtensorMapDataType, cuuint32_t, void*,
                          const cuuint64_t*, const cuuint64_t*,
                          const cuuint32_t*, const cuuint32_t*,
                          CUtensorMapInterleave, CUtensorMapSwizzle,
                          CUtensorMapL2promotion, CUtensorMapFloatOOBfill);

static void make_map3h(EncFn enc, CUtensorMap* m, void* ptr,
                       uint64_t d0, uint64_t d1, uint64_t d2,
                       uint64_t str1B, uint64_t str2B,
                       uint32_t b0, uint32_t b1, uint32_t b2)
{
    cuuint64_t dims[3] = {d0, d1, d2};
    cuuint64_t strides[2] = {str1B, str2B};
    cuuint32_t box[3] = {b0, b1, b2};
    cuuint32_t es[3] = {1, 1, 1};
    enc(m, CU_TENSOR_MAP_DATA_TYPE_FLOAT16, 3, ptr, dims, strides, box, es,
        CU_TENSOR_MAP_INTERLEAVE_NONE, CU_TENSOR_MAP_SWIZZLE_128B,
        CU_TENSOR_MAP_L2_PROMOTION_L2_128B, CU_TENSOR_MAP_FLOAT_OOB_FILL_NONE);
}

extern "C" void kernel_launch(void* const* d_in, const int* in_sizes, int n_in,
                              void* d_out, int out_size)
{
    const float* seqs     = (const float*)d_in[0];
    const int*   seq_lens = (const int*)  d_in[1];
    const float* h0       = (const float*)d_in[2];
    const float* c0       = (const float*)d_in[3];
    const float* Ww       = (const float*)d_in[4];
    const float* Wu       = (const float*)d_in[5];
    const float* Wv       = (const float*)d_in[6];
    const float* Wb       = (const float*)d_in[7];
    const float* Sw       = (const float*)d_in[8];
    const float* Su       = (const float*)d_in[9];
    const float* Sb       = (const float*)d_in[10];
    float* out = (float*)d_out;

    static EncFn enc = nullptr;
    static CUtensorMap mapHW, mapSQ, mapWB;
    static bool maps_ready = false;
    if (!maps_ready){
        cudaDriverEntryPointQueryResult qr;
        void* fn = nullptr;
        cudaGetDriverEntryPoint("cuTensorMapEncodeTiled", &fn, cudaEnableDefault, &qr);
        enc = (EncFn)fn;
        void *pHW = nullptr, *pSQ = nullptr, *pWB = nullptr;
        cudaGetSymbolAddress(&pHW, g_HW);
        cudaGetSymbolAddress(&pSQ, g_SQ);
        cudaGetSymbolAddress(&pWB, g_WB);
        // A views: (h=512, b=32, s=512) fp16; box (64,1,128)
        make_map3h(enc, &mapHW, pHW, 512, 32, 512, 512*2, 32*512*2, 64, 1, 128);
        make_map3h(enc, &mapSQ, pSQ, 512, 32, 512, 512*2, 32*512*2, 64, 1, 128);
        // B view: (k=2048, n=4096, 1) fp16; box (64,256,1)
        make_map3h(enc, &mapWB, pWB, 2048, 4096, 1,
                   (uint64_t)2048*2, (uint64_t)2048*4096*2, 64, 256, 1);
        cudaFuncSetAttribute(k_gemm, cudaFuncAttributeMaxDynamicSharedMemorySize, SMEM_TOTAL);
        maps_ready = true;
    }

    k_fused <<<13312, 256>>>(h0, seqs, Ww, Wu, Su, Sw, Sb, Wv, Wb, seq_lens);
    k_gemm  <<<dim3(16, 136), 256, SMEM_TOTAL>>>(mapHW, mapSQ, mapWB, seq_lens,
                                                 h0, Sw, Su, Sb);
    kg_part <<<dim3(32, 64), 512>>>(c0, seq_lens);
    kg_fin  <<<256, 256>>>(c0, out);
    k_epi   <<<8192, 256>>>(c0, seq_lens, out);
}

// round 16
// speedup vs baseline: 1.4190x; 1.4190x over previous
#include <cuda_runtime.h>
#include <cuda.h>
#include <cuda_fp16.h>
#include <math.h>
#include <stdint.h>

#define S_  512
#define Bb  32
#define Hh  512
#define Dd  512
#define Mrows (S_*Bb)          /* 16384 */
#define NCOLS 4096             /* 7 gates * 512 + 512 fi columns */
#define KTOT 2048

#if defined(__CUDA_ARCH_FEAT_SM103_ALL) || defined(__CUDA_ARCH_SPECIFIC__)
#define TC_PATH 1
#else
#define TC_PATH 0
#endif

static __device__ __half g_PRE[(size_t)Mrows * NCOLS];  // 128 MB (b-major rows: b*512+s)
static __device__ __half g_HW[(size_t)Mrows * Hh];      // masked h0[:-1], fp16 (s-major)
static __device__ __half g_SQ[(size_t)Mrows * Hh];      // seqs, fp16 (s-major)
static __device__ __half g_WB[(size_t)NCOLS * KTOT];    // packed fp16 weights [n][k]
static __device__ float g_HHATP[8 * Bb * Hh];
static __device__ float g_FG[Bb*Hh];
static __device__ float g_OG[Bb*Hh];
static __device__ float g_GW1[Bb*Hh];
static __device__ float g_VV[7*Bb*Hh];
static __device__ float g_GPl[64*Bb*Hh];
static __device__ float g_GPc[64*Bb*Hh];

__device__ __forceinline__ float sigf(float x){ return 1.0f/(1.0f + __expf(-x)); }

__device__ __forceinline__ uint32_t smem_u32(const void* p){
    uint32_t a;
    asm("{ .reg .u64 t; cvta.to.shared.u64 t, %1; cvt.u32.u64 %0, t; }"
        : "=r"(a) : "l"(p));
    return a;
}
__device__ __forceinline__ uint2 pack4h(float4 v){
    __half2 a = __floats2half2_rn(v.x, v.y);
    __half2 b = __floats2half2_rn(v.z, v.w);
    uint2 u;
    u.x = *(uint32_t*)&a;
    u.y = *(uint32_t*)&b;
    return u;
}
__device__ __forceinline__ float4 ld4h(const __half* p){
    __half2 a = *(const __half2*)p;
    __half2 b = *(const __half2*)(p + 2);
    return make_float4(__low2float(a), __high2float(a),
                       __low2float(b), __high2float(b));
}

#if TC_PATH
__device__ __forceinline__ uint32_t elect_one(){
    uint32_t p;
    asm volatile("{ .reg .pred P; elect.sync _|P, 0xFFFFFFFF; selp.b32 %0, 1, 0, P; }"
                 : "=r"(p));
    return p;
}
__device__ __forceinline__ void mbar_init(uint32_t a, uint32_t cnt){
    asm volatile("mbarrier.init.shared.b64 [%0], %1;" :: "r"(a), "r"(cnt) : "memory");
}
__device__ __forceinline__ void mbar_expect_tx(uint32_t a, uint32_t bytes){
    asm volatile("mbarrier.arrive.expect_tx.shared.b64 _, [%0], %1;"
                 :: "r"(a), "r"(bytes) : "memory");
}
__device__ __forceinline__ void mbar_wait(uint32_t a, uint32_t parity){
    asm volatile(
        "{\n\t.reg .pred P;\n\t"
        "WL_%=:\n\t"
        "mbarrier.try_wait.parity.acquire.cta.shared::cta.b64 P, [%0], %1;\n\t"
        "@P bra WD_%=;\n\t"
        "bra WL_%=;\n\t"
        "WD_%=:\n\t}"
        :: "r"(a), "r"(parity) : "memory");
}
__device__ __forceinline__ void tma_ld3(uint32_t smem, const void* map,
                                        int32_t x, int32_t y, int32_t z, uint32_t mbar){
    asm volatile(
        "cp.async.bulk.tensor.3d.shared::cta.global.tile.mbarrier::complete_tx::bytes "
        "[%0], [%1, {%2, %3, %4}], [%5];"
        :: "r"(smem), "l"(map), "r"(x), "r"(y), "r"(z), "r"(mbar) : "memory");
}
__device__ __forceinline__ void tmem_alloc(uint32_t dst_smem, uint32_t ncols){
    asm volatile("tcgen05.alloc.cta_group::1.sync.aligned.shared::cta.b32 [%0], %1;"
                 :: "r"(dst_smem), "r"(ncols) : "memory");
}
__device__ __forceinline__ void tmem_relinquish(){
    asm volatile("tcgen05.relinquish_alloc_permit.cta_group::1.sync.aligned;");
}
__device__ __forceinline__ void tmem_dealloc(uint32_t tmem, uint32_t ncols){
    asm volatile("tcgen05.dealloc.cta_group::1.sync.aligned.b32 %0, %1;"
                 :: "r"(tmem), "r"(ncols));
}
__device__ __forceinline__ void mma_f16(uint32_t d, uint64_t ad, uint64_t bd,
                                        uint32_t idesc, uint32_t en){
    asm volatile(
        "{\n\t.reg .pred p;\n\t"
        "setp.ne.u32 p, %4, 0;\n\t"
        "tcgen05.mma.cta_group::1.kind::f16 [%0], %1, %2, %3, p;\n\t}"
        :: "r"(d), "l"(ad), "l"(bd), "r"(idesc), "r"(en) : "memory");
}
__device__ __forceinline__ void mma_commit(uint32_t mbar){
    asm volatile("tcgen05.commit.cta_group::1.mbarrier::arrive::one.shared::cluster.b64 [%0];"
                 :: "r"(mbar) : "memory");
}
__device__ __forceinline__ void tc_fence_after(){
    asm volatile("tcgen05.fence::after_thread_sync;" ::: "memory");
}
__device__ __forceinline__ void tc_fence_before(){
    asm volatile("tcgen05.fence::before_thread_sync;" ::: "memory");
}
__device__ __forceinline__ void tmem_wait_ld(){
    asm volatile("tcgen05.wait::ld.sync.aligned;" ::: "memory");
}
__device__ __forceinline__ void tmem_ld32(uint32_t* r, uint32_t addr){
    asm volatile(
        "tcgen05.ld.sync.aligned.32x32b.x32.b32 "
        "{%0, %1, %2, %3, %4, %5, %6, %7, "
        " %8, %9, %10, %11, %12, %13, %14, %15, "
        " %16, %17, %18, %19, %20, %21, %22, %23, "
        " %24, %25, %26, %27, %28, %29, %30, %31}, [%32];"
        : "=r"(r[0]),  "=r"(r[1]),  "=r"(r[2]),  "=r"(r[3]),
          "=r"(r[4]),  "=r"(r[5]),  "=r"(r[6]),  "=r"(r[7]),
          "=r"(r[8]),  "=r"(r[9]),  "=r"(r[10]), "=r"(r[11]),
          "=r"(r[12]), "=r"(r[13]), "=r"(r[14]), "=r"(r[15]),
          "=r"(r[16]), "=r"(r[17]), "=r"(r[18]), "=r"(r[19]),
          "=r"(r[20]), "=r"(r[21]), "=r"(r[22]), "=r"(r[23]),
          "=r"(r[24]), "=r"(r[25]), "=r"(r[26]), "=r"(r[27]),
          "=r"(r[28]), "=r"(r[29]), "=r"(r[30]), "=r"(r[31])
        : "r"(addr));
}
static constexpr uint64_t DESC_BASE =
    (2ull << 61) | (1ull << 46) | (64ull << 32) | (1ull << 16);
#define IDESC_F16 ((1u<<4)|((128u/8u)<<17)|((128u/16u)<<24))
#endif  // TC_PATH

#define NSTAGE 2
#define STAGE_BYTES 49152            /* A 16KB + B 32KB (fp16, K=64) */
#define SMEM_TOTAL (1024 + NSTAGE*STAGE_BYTES)   /* 99328 -> 2 CTAs/SM */

// ------------------------------------------------------------------
// k_fused: block-range dispatch of four independent prep jobs.
//   [0, 8192)       : masked fp16 copy h0->g_HW ; seqs->g_SQ (8 floats/thr)
//   [8192, 12288)   : packed fp16 weight matrix g_WB
//   [12288, 12800)  : h_hat partial sums (from h0 + mask, fp32)
//   [12800, 13312)  : GEMV targets 2..9 (gw1, VV[0..6]) — input-only deps
// ------------------------------------------------------------------
__global__ void __launch_bounds__(256)
k_fused(const float* __restrict__ h0, const float* __restrict__ seqs,
        const float* __restrict__ Ww, const float* __restrict__ Wu,
        const float* __restrict__ Su, const float* __restrict__ Sw,
        const float* __restrict__ Sb, const float* __restrict__ Wv,
        const float* __restrict__ Wb, const int* __restrict__ seq_lens)
{
    const int bid = blockIdx.x;
    const int tid = threadIdx.x;
    __shared__ float sx1[4][512];

    if (bid < 8192){
        size_t idx = (size_t)bid * 256 + tid;        // 8-float unit
        const size_t NU = (size_t)Mrows * Hh / 8;    // 1M units per array
        if (idx < NU){
            size_t e = idx << 3;
            int r = (int)(e >> 9);
            int b = r & 31;
            int s = r >> 5;
            float4 v0 = make_float4(0.f,0.f,0.f,0.f);
            float4 v1 = make_float4(0.f,0.f,0.f,0.f);
            if (s < seq_lens[b]){
                v0 = *(const float4*)(h0 + e);
                v1 = *(const float4*)(h0 + e + 4);
            }
            *(uint2*)(g_HW + e)     = pack4h(v0);
            *(uint2*)(g_HW + e + 4) = pack4h(v1);
        } else {
            size_t e = (idx - NU) << 3;
            float4 v0 = *(const float4*)(seqs + e);
            float4 v1 = *(const float4*)(seqs + e + 4);
            *(uint2*)(g_SQ + e)     = pack4h(v0);
            *(uint2*)(g_SQ + e + 4) = pack4h(v1);
        }
    } else if (bid < 12288){
        int n = bid - 8192;
        __half* dst = g_WB + (size_t)n * KTOT;
        #pragma unroll
        for (int half = 0; half < 2; ++half){
            int k4 = tid*4 + half*1024;
            float4 v;
            if (n < 3584){
                int g = n >> 9, h = n & 511;
                int seg = k4 >> 9, kk = k4 & 511;
                const float* src = (seg < 3)
                    ? (Ww + ((size_t)(g*512 + h))*1536 + seg*512 + kk)
                    : (Wu + ((size_t)(g*512 + h))*512 + kk);
                v = *(const float4*)src;
            } else {
                int h = n - 3584;
                if (k4 < 512) v = *(const float4*)(Su + ((size_t)(512 + h))*512 + k4);
                else          v = make_float4(0.f,0.f,0.f,0.f);
            }
            *(uint2*)(dst + k4) = pack4h(v);
        }
    } else if (bid < 12800){
        int idx = bid - 12288;       // 0..511
        int b    = idx & 31;
        int sc   = (idx >> 5) & 7;
        int half = idx >> 8;
        int h = half*256 + tid;
        int len = seq_lens[b];
        int s1 = sc*64;
        int s2 = min(s1 + 64, len);
        const float* p = h0 + ((size_t)s1*32 + b)*512 + h;
        float acc = 0.f;
        for (int s = s1; s < s2; ++s){
            acc += *p;
            p += 16384;
        }
        g_HHATP[(size_t)sc*16384 + b*512 + h] = acc;
    } else {
        // GEMV targets 2..9: 8 targets x 64 blocks each
        int idx = bid - 12800;           // 0..511
        const int target = 2 + (idx >> 6);
        int rest = idx & 63;
        const int bg = (rest >> 3) << 2; // 8 b-groups of 4
        const int hz = (rest & 7) << 6;  // 8 h-groups of 64

        for (int i = tid; i < 4*512; i += 256){
            int bb = i >> 9, k = i & 511;
            int b = bg + bb;
            sx1[bb][k] = h0[((size_t)(S_*Bb) + b)*Hh + k];
        }
        __syncthreads();

        const int warp = tid >> 5, lane = tid & 31;
        const int hh = hz + warp*8;

        float acc[4][8];
        #pragma unroll
        for (int bb=0;bb<4;bb++)
            #pragma unroll
            for (int j=0;j<8;j++) acc[bb][j] = 0.f;

        const float* wb1 = (target == 2)
            ? (Sw + ((size_t)(512 + hh))*512)
            : (Wv + ((size_t)((target-3)*512 + hh))*512);

        #pragma unroll 4
        for (int i = 0; i < 16; ++i){
            int k = lane + (i << 5);
            float w[8];
            #pragma unroll
            for (int j=0;j<8;j++) w[j] = wb1[(size_t)j*512 + k];
            #pragma unroll
            for (int bb=0;bb<4;bb++){
                float a = sx1[bb][k];
                #pragma unroll
                for (int j=0;j<8;j++) acc[bb][j] += a * w[j];
            }
        }

        #pragma unroll
        for (int bb=0;bb<4;bb++)
            #pragma unroll
            for (int j=0;j<8;j++){
                float v = acc[bb][j];
                #pragma unroll
                for (int o=16;o;o>>=1) v += __shfl_xor_sync(0xffffffffu, v, o);
                acc[bb][j] = v;
            }

        if (lane == 0){
            #pragma unroll
            for (int bb=0;bb<4;bb++){
                int b = bg + bb;
                #pragma unroll
                for (int j=0;j<8;j++){
                    int h = hh + j;
                    float v = acc[bb][j];
                    if (target == 2) g_GW1[b*512 + h] = v + Sb[512 + h];
                    else {
                        int g = target - 3;
                        g_VV[((size_t)g*Bb + b)*Hh + h] = v + Wb[g*512 + h];
                    }
                }
            }
        }
    }
}

// ------------------------------------------------------------------
// main GEMM (fp16 operands, fp32 accum). Tile M=128 x N=256.
// K-chunk = 64 fp16 (128B rows). grid(16,136), 2 CTAs/SM.
//   mb < 128 : GEMM tiles (R8-proven path)
//   mb >= 128: fg/og GEMV CTAs (fold of old k_small01; tail-scheduled)
// ------------------------------------------------------------------
__global__ void __launch_bounds__(256, 2)
k_gemm(const __grid_constant__ CUtensorMap mapHW,
       const __grid_constant__ CUtensorMap mapSQ,
       const __grid_constant__ CUtensorMap mapWB,
       const int* __restrict__ seq_lens,
       const float* __restrict__ h0,
       const float* __restrict__ Sw, const float* __restrict__ Su,
       const float* __restrict__ Sb)
{
    extern __shared__ char smem_raw[];
    const int tid = threadIdx.x;
    const int nb = blockIdx.x;     // 0..15
    const int mb = blockIdx.y;     // 0..135

    if (mb >= 128){
        // ---------------- fg/og GEMV (uses dynamic smem) ----------------
        int idx2 = (mb - 128)*16 + nb;     // 0..127
        const int target = idx2 >> 6;      // 0=fg, 1=og
        int rest = idx2 & 63;
        const int bg = (rest >> 3) << 2;
        const int hz = (rest & 7) << 6;
        float* sx1 = (float*)smem_raw;          // 4x512
        float* sx2 = sx1 + 4*512;               // 4x512

        for (int i = tid; i < 4*512; i += 256){
            int bb = i >> 9, k = i & 511;
            int b = bg + bb;
            sx1[bb*512 + k] = h0[((size_t)(S_*Bb) + b)*Hh + k];
            float s8 = 0.f;
            #pragma unroll
            for (int sc = 0; sc < 8; ++sc)
                s8 += g_HHATP[(size_t)sc*16384 + b*512 + k];
            sx2[bb*512 + k] = s8 * (1.0f/512.0f);
        }
        __syncthreads();

        const int warp = tid >> 5, lane = tid & 31;
        const int hh = hz + warp*8;
        const int si = (target==0) ? 0 : 2;

        float acc[4][8];
        #pragma unroll
        for (int bb=0;bb<4;bb++)
            #pragma unroll
            for (int j=0;j<8;j++) acc[bb][j] = 0.f;

        const float* wb1 = Sw + ((size_t)(si*512 + hh))*512;
        const float* wb2 = Su + ((size_t)(si*512 + hh))*512;

        #pragma unroll 4
        for (int i = 0; i < 16; ++i){
            int k = lane + (i << 5);
            float w1[8], w2[8];
            #pragma unroll
            for (int j=0;j<8;j++){ w1[j] = wb1[(size_t)j*512 + k]; w2[j] = wb2[(size_t)j*512 + k]; }
            #pragma unroll
            for (int bb=0;bb<4;bb++){
                float a1 = sx1[bb*512 + k];
                float a2 = sx2[bb*512 + k];
                #pragma unroll
                for (int j=0;j<8;j++) acc[bb][j] += a1*w1[j] + a2*w2[j];
            }
        }

        #pragma unroll
        for (int bb=0;bb<4;bb++)
            #pragma unroll
            for (int j=0;j<8;j++){
                float v = acc[bb][j];
                #pragma unroll
                for (int o=16;o;o>>=1) v += __shfl_xor_sync(0xffffffffu, v, o);
                acc[bb][j] = v;
            }

        if (lane == 0){
            #pragma unroll
            for (int bb=0;bb<4;bb++){
                int b = bg + bb;
                #pragma unroll
                for (int j=0;j<8;j++){
                    int h = hh + j;
                    float v = sigf(acc[bb][j] + Sb[si*512 + h]);
                    (target==0 ? g_FG : g_OG)[b*512 + h] = v;
                }
            }
        }
        return;
    }

    const int b  = mb >> 2;
    const int s0 = (mb & 3) << 7;
    if (s0 >= seq_lens[b]) return;

    const bool isFi = (nb >= 14);
    const int NC = isFi ? 8 : 32;

#if TC_PATH
    char* sbp = (char*)(((uintptr_t)smem_raw + 1023) & ~(uintptr_t)1023);
    const uint32_t sbu = smem_u32(sbp);
    const int warp = tid >> 5;

    if (tid == 0){
        #pragma unroll
        for (int s = 0; s < NSTAGE; ++s){
            mbar_init(sbu + 16 + 8*s, 1);     // full
            mbar_init(sbu + 48 + 8*s, 1);     // done
        }
        mbar_init(sbu + 80, 1);               // final
    }
    if (warp == 0){ tmem_alloc(sbu, 256); tmem_relinquish(); }
    __syncthreads();
    uint32_t tmem;
    asm volatile("ld.shared.b32 %0, [%1];" : "=r"(tmem) : "r"(sbu));

    if (warp == 0){
        if (elect_one()){
            for (int c = 0; c < NC; ++c){
                const int st = c % NSTAGE;
                const int q  = c / NSTAGE;
                if (c >= NSTAGE) mbar_wait(sbu + 48 + 8*st, (q - 1) & 1);
                const uint32_t full = sbu + 16 + 8*st;
                mbar_expect_tx(full, STAGE_BYTES);
                const uint32_t aAddr = sbu + 1024 + st*STAGE_BYTES;
                const uint32_t bAddr = aAddr + 16384;
                if (isFi){
                    tma_ld3(aAddr, &mapHW, c*64, b, s0, full);
                } else {
                    const int seg = c >> 3;
                    const int kc  = (c & 7) << 6;
                    if (seg < 3) tma_ld3(aAddr, &mapHW, kc, b, s0 + seg - 1, full);
                    else         tma_ld3(aAddr, &mapSQ, kc, b, s0, full);
                }
                tma_ld3(bAddr, &mapWB, c*64, nb*256, 0, full);
            }
        }
    } else if (warp == 1){
        if (elect_one()){
            for (int c = 0; c < NC; ++c){
                const int st = c % NSTAGE;
                const int q  = c / NSTAGE;
                mbar_wait(sbu + 16 + 8*st, q & 1);
                const uint32_t aAddr = sbu + 1024 + st*STAGE_BYTES;
                const uint32_t bAddr = aAddr + 16384;
                uint64_t ad  = DESC_BASE | ((aAddr >> 4) & 0x3FFFu);
                uint64_t bd0 = DESC_BASE | ((bAddr >> 4) & 0x3FFFu);
                uint64_t bd1 = bd0 + 1024;
                #pragma unroll
                for (int ks = 0; ks < 4; ++ks){
                    uint32_t en = (c > 0 || ks > 0) ? 1u : 0u;
                    mma_f16(tmem,       ad + 2*ks, bd0 + 2*ks, IDESC_F16, en);
                    mma_f16(tmem + 128, ad + 2*ks, bd1 + 2*ks, IDESC_F16, en);
                }
                mma_commit(sbu + 48 + 8*st);
            }
            mma_commit(sbu + 80);
        }
    }

    mbar_wait(sbu + 80, 0);
    tc_fence_after();

    // epilogue: TMEM f32 -> fp16 PRE
    {
        const int w = tid >> 5, lane = tid & 31;
        const int sub = w & 3;
        const int colh = (w >> 2) * 128;
        const uint32_t tb = tmem + ((uint32_t)sub << 21) + colh;
        __half* dst0 = g_PRE + ((size_t)(b*512 + s0 + sub*32 + lane))*NCOLS + nb*256 + colh;
        #pragma unroll
        for (int qq = 0; qq < 4; ++qq){
            uint32_t r[32];
            tmem_ld32(r, tb + qq*32);
            tmem_wait_ld();
            uint32_t hp[16];
            #pragma unroll
            for (int k = 0; k < 16; ++k){
                __half2 h2 = __floats2half2_rn(__uint_as_float(r[2*k]),
                                               __uint_as_float(r[2*k+1]));
                hp[k] = *(uint32_t*)&h2;
            }
            __half* dst = dst0 + qq*32;
            #pragma unroll
            for (int k = 0; k < 4; ++k)
                *(uint4*)(dst + k*8) = *(const uint4*)(hp + k*4);
        }
    }
    tc_fence_before();
    __syncthreads();
    if (warp == 0) tmem_dealloc(tmem, 256);

#else
    // ================= SIMT fallback (generic pass; not expected to run) =================
    float (*As)[132] = (float (*)[132])smem_raw;
    float (*Bs)[132] = (float (*)[132])(smem_raw + 16*132*4);

    const int arow = tid >> 2;
    const int acol = (tid & 3) << 2;
    const int m1 = arow, m2 = arow + 64;
    const int bcol = tid >> 2;
    const int bkg  = (tid & 3) << 2;
    const int ty8 = (tid >> 4) << 3;
    const int tx8 = (tid & 15) << 3;
    const int Kmax = isFi ? 512 : 2048;

    for (int p = 0; p < 2; ++p){
        const int coln = nb*256 + p*128;
        float acc[8][8];
        #pragma unroll
        for (int i=0;i<8;i++)
            #pragma unroll
            for (int j=0;j<8;j++) acc[i][j]=0.f;

        for (int k0 = 0; k0 < Kmax; k0 += 16){
            const int seg = isFi ? 1 : (k0 >> 9);
            const int kc  = isFi ? k0 : (k0 & 511);
            const int sh  = isFi ? 0 : (seg - 1);

            float4 a1, a2;
            if (!isFi && seg == 3){
                a1 = ld4h(g_SQ + ((size_t)((s0+m1)*32 + b))*512 + kc + acol);
                a2 = ld4h(g_SQ + ((size_t)((s0+m2)*32 + b))*512 + kc + acol);
            } else {
                int sp1 = s0 + m1 + sh, sp2 = s0 + m2 + sh;
                a1 = ((unsigned)sp1 < 512u) ? ld4h(g_HW + ((size_t)(sp1*32 + b))*512 + kc + acol)
                                            : make_float4(0.f,0.f,0.f,0.f);
                a2 = ((unsigned)sp2 < 512u) ? ld4h(g_HW + ((size_t)(sp2*32 + b))*512 + kc + acol)
                                            : make_float4(0.f,0.f,0.f,0.f);
            }
            float4 w1 = ld4h(g_WB + ((size_t)(coln + bcol))*KTOT + k0 + bkg);
            float4 w2 = ld4h(g_WB + ((size_t)(coln + bcol + 64))*KTOT + k0 + bkg);
            __syncthreads();
            As[acol+0][m1] = a1.x; As[acol+1][m1] = a1.y;
            As[acol+2][m1] = a1.z; As[acol+3][m1] = a1.w;
            As[acol+0][m2] = a2.x; As[acol+1][m2] = a2.y;
            As[acol+2][m2] = a2.z; As[acol+3][m2] = a2.w;
            Bs[bkg+0][bcol] = w1.x; Bs[bkg+1][bcol] = w1.y;
            Bs[bkg+2][bcol] = w1.z; Bs[bkg+3][bcol] = w1.w;
            Bs[bkg+0][bcol+64] = w2.x; Bs[bkg+1][bcol+64] = w2.y;
            Bs[bkg+2][bcol+64] = w2.z; Bs[bkg+3][bcol+64] = w2.w;
            __syncthreads();
            #pragma unroll
            for (int kk = 0; kk < 16; ++kk){
                float a[8], bv[8];
                *(float4*)&a[0]  = *(const float4*)&As[kk][ty8];
                *(float4*)&a[4]  = *(const float4*)&As[kk][ty8+4];
                *(float4*)&bv[0] = *(const float4*)&Bs[kk][tx8];
                *(float4*)&bv[4] = *(const float4*)&Bs[kk][tx8+4];
                #pragma unroll
                for (int i=0;i<8;i++)
                    #pragma unroll
                    for (int j=0;j<8;j++)
                        acc[i][j] += a[i]*bv[j];
            }
        }
        #pragma unroll
        for (int i=0;i<8;i++){
            __half* pp = g_PRE + ((size_t)(b*512 + s0 + ty8 + i))*NCOLS + coln + tx8;
            *(uint2*)pp     = pack4h(make_float4(acc[i][0],acc[i][1],acc[i][2],acc[i][3]));
            *(uint2*)(pp+4) = pack4h(make_float4(acc[i][4],acc[i][5],acc[i][6],acc[i][7]));
        }
        __syncthreads();
    }
#endif
}

// ------------------------------------------------------------------
// global cell, stage 1: partial (l, cacc) over 8-s chunks
// ------------------------------------------------------------------
__global__ void kg_part(const float* __restrict__ c0, const int* __restrict__ seq_lens)
{
    int b = blockIdx.x, sc = blockIdx.y, h = threadIdx.x;
    int len = seq_lens[b];
    int s1 = sc*8;
    int s2 = min(s1 + 8, len);
    float g1 = g_GW1[b*512 + h];
    const __half* prep = g_PRE + ((size_t)(b*512 + s1))*NCOLS + 3584 + h;
    const float* cp    = c0 + ((size_t)s1*32 + b)*512 + h;
    float l = 0.f, cacc = 0.f;
    for (int s = s1; s < s2; ++s){
        float e = __expf(sigf(g1 + __half2float(*prep)));
        l += e;
        cacc += e * (*cp);
        prep += NCOLS;
        cp   += 16384;
    }
    g_GPl[(size_t)sc*16384 + b*512 + h] = l;
    g_GPc[(size_t)sc*16384 + b*512 + h] = cacc;
}

// ------------------------------------------------------------------
// global cell, stage 2: reduce + c_g / h_g.
// 256 blocks x 256 threads; 4 quarters of 16 chunks per (b,h),
// coalesced loads (warp lanes = consecutive elements), smem combine.
// ------------------------------------------------------------------
__global__ void __launch_bounds__(256)
kg_fin(const float* __restrict__ c0, float* __restrict__ out)
{
    __shared__ float sl[256], sc_[256];
    const int tid = threadIdx.x;
    const int e = blockIdx.x*64 + (tid & 63);    // element index in [0,16384)
    const int q = tid >> 6;                      // quarter 0..3
    float l = 0.f, cacc = 0.f;
    #pragma unroll
    for (int i = 0; i < 16; ++i){
        int sc = q*16 + i;
        l    += g_GPl[(size_t)sc*16384 + e];
        cacc += g_GPc[(size_t)sc*16384 + e];
    }
    sl[tid] = l; sc_[tid] = cacc;
    __syncthreads();
    if (tid < 64){
        l    = sl[tid]  + sl[tid+64]  + sl[tid+128]  + sl[tid+192];
        cacc = sc_[tid] + sc_[tid+64] + sc_[tid+128] + sc_[tid+192];
        int b = e >> 9;
        int h = e & 511;
        size_t gidx = ((size_t)(S_*Bb) + b)*Hh + h;
        float cg = g_FG[b*512 + h]*c0[gidx] + cacc / l;
        float hg = g_OG[b*512 + h]*tanhf(cg);
        const size_t CT = (size_t)(S_+1)*Bb*Hh;
        out[gidx] = hg;
        out[CT + gidx] = cg;
    }
}

// ------------------------------------------------------------------
// window cell epilogue (4 h per thread: uint2 PRE, float4 c0/VV/out)
// ------------------------------------------------------------------
__global__ void __launch_bounds__(256)
k_epi(const float* __restrict__ c0, const int* __restrict__ seq_lens,
      float* __restrict__ out)
{
    size_t idx = (size_t)blockIdx.x*256 + threadIdx.x;   // 4h unit index
    int h4 = (int)(idx & 127);
    size_t rc = idx >> 7;          // s*32 + b
    int b = (int)(rc & 31);
    int s = (int)(rc >> 5);
    int len = seq_lens[b];
    const size_t CT = (size_t)(S_+1)*Bb*Hh;
    float4* o1 = (float4*)(out + rc*512 + h4*4);
    float4* o2 = (float4*)(out + CT + rc*512 + h4*4);
    if (s >= len){
        *o1 = make_float4(0.f, 0.f, 0.f, 0.f);
        *o2 = make_float4(0.f, 0.f, 0.f, 0.f);
        return;
    }

    const __half* prow = g_PRE + ((size_t)b*512 + s)*NCOLS + h4*4;
    float px[7][4];
    #pragma unroll
    for (int g = 0; g < 7; ++g){
        uint2 raw = *(const uint2*)(prow + g*512);
        __half2 a = *(__half2*)&raw.x;
        __half2 bb2 = *(__half2*)&raw.y;
        float4 vv = *(const float4*)(g_VV + ((size_t)g*Bb + b)*Hh + h4*4);
        px[g][0] = __low2float(a)   + vv.x;
        px[g][1] = __high2float(a)  + vv.y;
        px[g][2] = __low2float(bb2) + vv.z;
        px[g][3] = __high2float(bb2)+ vv.w;
    }

    float4 cl  = (s >= 1) ? *(const float4*)(c0 + (rc-32)*Hh + h4*4) : make_float4(0.f,0.f,0.f,0.f);
    float4 cc  = *(const float4*)(c0 + rc*Hh + h4*4);
    float4 cr  = (s+1 < S_ && s+1 < len) ? *(const float4*)(c0 + (rc+32)*Hh + h4*4)
                                         : make_float4(0.f,0.f,0.f,0.f);
    float4 cg1 = *(const float4*)(c0 + ((size_t)(S_*Bb) + b)*Hh + h4*4);

    float clv[4] = {cl.x, cl.y, cl.z, cl.w};
    float ccv[4] = {cc.x, cc.y, cc.z, cc.w};
    float crv[4] = {cr.x, cr.y, cr.z, cr.w};
    float cgv[4] = {cg1.x, cg1.y, cg1.z, cg1.w};
    float hw[4], cw4[4];
    #pragma unroll
    for (int j = 0; j < 4; ++j){
        float si_ = sigf(px[0][j]);
        float sl_ = sigf(px[1][j]);
        float sr_ = sigf(px[2][j]);
        float sf_ = sigf(px[3][j]);
        float ss_ = sigf(px[4][j]);
        float so_ = sigf(px[5][j]);
        float u_  = tanhf(px[6][j]);

        float e0 = __expf(sl_);
        float e1 = __expf(sf_);
        float e2 = __expf(sr_);
        float e3 = __expf(ss_);
        float e4 = __expf(si_);
        float inv = 1.f/(e0+e1+e2+e3+e4);

        float cw = (e0*clv[j] + e1*ccv[j] + e2*crv[j] + e3*cgv[j] + e4*u_) * inv;
        hw[j] = so_ * tanhf(cw);
        cw4[j] = cw;
    }
    *o1 = make_float4(hw[0], hw[1], hw[2], hw[3]);
    *o2 = make_float4(cw4[0], cw4[1], cw4[2], cw4[3]);
}

// ------------------------------------------------------------------
// host
// ------------------------------------------------------------------
typedef CUresult (*EncFn)(CUtensorMap*, CUtensorMapDataType, cuuint32_t, void*,
                          const cuuint64_t*, const cuuint64_t*,
                          const cuuint32_t*, const cuuint32_t*,
                          CUtensorMapInterleave, CUtensorMapSwizzle,
                          CUtensorMapL2promotion, CUtensorMapFloatOOBfill);

static void make_map3h(EncFn enc, CUtensorMap* m, void* ptr,
                       uint64_t d0, uint64_t d1, uint64_t d2,
                       uint64_t str1B, uint64_t str2B,
                       uint32_t b0, uint32_t b1, uint32_t b2)
{
    cuuint64_t dims[3] = {d0, d1, d2};
    cuuint64_t strides[2] = {str1B, str2B};
    cuuint32_t box[3] = {b0, b1, b2};
    cuuint32_t es[3] = {1, 1, 1};
    enc(m, CU_TENSOR_MAP_DATA_TYPE_FLOAT16, 3, ptr, dims, strides, box, es,
        CU_TENSOR_MAP_INTERLEAVE_NONE, CU_TENSOR_MAP_SWIZZLE_128B,
        CU_TENSOR_MAP_L2_PROMOTION_L2_128B, CU_TENSOR_MAP_FLOAT_OOB_FILL_NONE);
}

extern "C" void kernel_launch(void* const* d_in, const int* in_sizes, int n_in,
                              void* d_out, int out_size)
{
    const float* seqs     = (const float*)d_in[0];
    const int*   seq_lens = (const int*)  d_in[1];
    const float* h0       = (const float*)d_in[2];
    const float* c0       = (const float*)d_in[3];
    const float* Ww       = (const float*)d_in[4];
    const float* Wu       = (const float*)d_in[5];
    const float* Wv       = (const float*)d_in[6];
    const float* Wb       = (const float*)d_in[7];
    const float* Sw       = (const float*)d_in[8];
    const float* Su       = (const float*)d_in[9];
    const float* Sb       = (const float*)d_in[10];
    float* out = (float*)d_out;

    static EncFn enc = nullptr;
    static CUtensorMap mapHW, mapSQ, mapWB;
    static bool maps_ready = false;
    if (!maps_ready){
        cudaDriverEntryPointQueryResult qr;
        void* fn = nullptr;
        cudaGetDriverEntryPoint("cuTensorMapEncodeTiled", &fn, cudaEnableDefault, &qr);
        enc = (EncFn)fn;
        void *pHW = nullptr, *pSQ = nullptr, *pWB = nullptr;
        cudaGetSymbolAddress(&pHW, g_HW);
        cudaGetSymbolAddress(&pSQ, g_SQ);
        cudaGetSymbolAddress(&pWB, g_WB);
        // A views: (h=512, b=32, s=512) fp16; box (64,1,128)
        make_map3h(enc, &mapHW, pHW, 512, 32, 512, 512*2, 32*512*2, 64, 1, 128);
        make_map3h(enc, &mapSQ, pSQ, 512, 32, 512, 512*2, 32*512*2, 64, 1, 128);
        // B view: (k=2048, n=4096, 1) fp16; box (64,256,1)
        make_map3h(enc, &mapWB, pWB, 2048, 4096, 1,
                   (uint64_t)2048*2, (uint64_t)2048*4096*2, 64, 256, 1);
        cudaFuncSetAttribute(k_gemm, cudaFuncAttributeMaxDynamicSharedMemorySize, SMEM_TOTAL);
        maps_ready = true;
    }

    k_fused <<<13312, 256>>>(h0, seqs, Ww, Wu, Su, Sw, Sb, Wv, Wb, seq_lens);
    k_gemm  <<<dim3(16, 136), 256, SMEM_TOTAL>>>(mapHW, mapSQ, mapWB, seq_lens,
                                                 h0, Sw, Su, Sb);
    kg_part <<<dim3(32, 64), 512>>>(c0, seq_lens);
    kg_fin  <<<256, 256>>>(c0, out);
    k_epi   <<<8192, 256>>>(c0, seq_lens, out);
}

// round 17
// speedup vs baseline: 1.4609x; 1.0295x over previous
#include <cuda_runtime.h>
#include <cuda.h>
#include <cuda_fp16.h>
#include <math.h>
#include <stdint.h>

#define S_  512
#define Bb  32
#define Hh  512
#define Dd  512
#define Mrows (S_*Bb)          /* 16384 */
#define NCOLS 4096             /* 7 gates * 512 + 512 fi columns */
#define KTOT 2048

#if defined(__CUDA_ARCH_FEAT_SM103_ALL) || defined(__CUDA_ARCH_SPECIFIC__)
#define TC_PATH 1
#else
#define TC_PATH 0
#endif

static __device__ __half g_PRE[(size_t)Mrows * NCOLS];  // 128 MB (b-major rows: b*512+s)
static __device__ __half g_HW[(size_t)Mrows * Hh];      // masked h0[:-1], fp16 (s-major)
static __device__ __half g_SQ[(size_t)Mrows * Hh];      // seqs, fp16 (s-major)
static __device__ __half g_WB[(size_t)NCOLS * KTOT];    // packed fp16 weights [n][k]
static __device__ float g_HHATP[8 * Bb * Hh];
static __device__ float g_FG[Bb*Hh];
static __device__ float g_OG[Bb*Hh];
static __device__ float g_GW1[Bb*Hh];
static __device__ float g_VV[7*Bb*Hh];
static __device__ float g_GPl[64*Bb*Hh];
static __device__ float g_GPc[64*Bb*Hh];

__device__ __forceinline__ float sigf(float x){ return 1.0f/(1.0f + __expf(-x)); }

__device__ __forceinline__ uint32_t smem_u32(const void* p){
    uint32_t a;
    asm("{ .reg .u64 t; cvta.to.shared.u64 t, %1; cvt.u32.u64 %0, t; }"
        : "=r"(a) : "l"(p));
    return a;
}
__device__ __forceinline__ uint2 pack4h(float4 v){
    __half2 a = __floats2half2_rn(v.x, v.y);
    __half2 b = __floats2half2_rn(v.z, v.w);
    uint2 u;
    u.x = *(uint32_t*)&a;
    u.y = *(uint32_t*)&b;
    return u;
}
__device__ __forceinline__ float4 ld4h(const __half* p){
    __half2 a = *(const __half2*)p;
    __half2 b = *(const __half2*)(p + 2);
    return make_float4(__low2float(a), __high2float(a),
                       __low2float(b), __high2float(b));
}

#if TC_PATH
__device__ __forceinline__ uint32_t elect_one(){
    uint32_t p;
    asm volatile("{ .reg .pred P; elect.sync _|P, 0xFFFFFFFF; selp.b32 %0, 1, 0, P; }"
                 : "=r"(p));
    return p;
}
__device__ __forceinline__ void mbar_init(uint32_t a, uint32_t cnt){
    asm volatile("mbarrier.init.shared.b64 [%0], %1;" :: "r"(a), "r"(cnt) : "memory");
}
__device__ __forceinline__ void mbar_expect_tx(uint32_t a, uint32_t bytes){
    asm volatile("mbarrier.arrive.expect_tx.shared.b64 _, [%0], %1;"
                 :: "r"(a), "r"(bytes) : "memory");
}
__device__ __forceinline__ void mbar_wait(uint32_t a, uint32_t parity){
    asm volatile(
        "{\n\t.reg .pred P;\n\t"
        "WL_%=:\n\t"
        "mbarrier.try_wait.parity.acquire.cta.shared::cta.b64 P, [%0], %1;\n\t"
        "@P bra WD_%=;\n\t"
        "bra WL_%=;\n\t"
        "WD_%=:\n\t}"
        :: "r"(a), "r"(parity) : "memory");
}
__device__ __forceinline__ void tma_ld3(uint32_t smem, const void* map,
                                        int32_t x, int32_t y, int32_t z, uint32_t mbar){
    asm volatile(
        "cp.async.bulk.tensor.3d.shared::cta.global.tile.mbarrier::complete_tx::bytes "
        "[%0], [%1, {%2, %3, %4}], [%5];"
        :: "r"(smem), "l"(map), "r"(x), "r"(y), "r"(z), "r"(mbar) : "memory");
}
__device__ __forceinline__ void tmem_alloc(uint32_t dst_smem, uint32_t ncols){
    asm volatile("tcgen05.alloc.cta_group::1.sync.aligned.shared::cta.b32 [%0], %1;"
                 :: "r"(dst_smem), "r"(ncols) : "memory");
}
__device__ __forceinline__ void tmem_relinquish(){
    asm volatile("tcgen05.relinquish_alloc_permit.cta_group::1.sync.aligned;");
}
__device__ __forceinline__ void tmem_dealloc(uint32_t tmem, uint32_t ncols){
    asm volatile("tcgen05.dealloc.cta_group::1.sync.aligned.b32 %0, %1;"
                 :: "r"(tmem), "r"(ncols));
}
__device__ __forceinline__ void mma_f16(uint32_t d, uint64_t ad, uint64_t bd,
                                        uint32_t idesc, uint32_t en){
    asm volatile(
        "{\n\t.reg .pred p;\n\t"
        "setp.ne.u32 p, %4, 0;\n\t"
        "tcgen05.mma.cta_group::1.kind::f16 [%0], %1, %2, %3, p;\n\t}"
        :: "r"(d), "l"(ad), "l"(bd), "r"(idesc), "r"(en) : "memory");
}
__device__ __forceinline__ void mma_commit(uint32_t mbar){
    asm volatile("tcgen05.commit.cta_group::1.mbarrier::arrive::one.shared::cluster.b64 [%0];"
                 :: "r"(mbar) : "memory");
}
__device__ __forceinline__ void tc_fence_after(){
    asm volatile("tcgen05.fence::after_thread_sync;" ::: "memory");
}
__device__ __forceinline__ void tc_fence_before(){
    asm volatile("tcgen05.fence::before_thread_sync;" ::: "memory");
}
__device__ __forceinline__ void tmem_wait_ld(){
    asm volatile("tcgen05.wait::ld.sync.aligned;" ::: "memory");
}
__device__ __forceinline__ void tmem_ld32(uint32_t* r, uint32_t addr){
    asm volatile(
        "tcgen05.ld.sync.aligned.32x32b.x32.b32 "
        "{%0, %1, %2, %3, %4, %5, %6, %7, "
        " %8, %9, %10, %11, %12, %13, %14, %15, "
        " %16, %17, %18, %19, %20, %21, %22, %23, "
        " %24, %25, %26, %27, %28, %29, %30, %31}, [%32];"
        : "=r"(r[0]),  "=r"(r[1]),  "=r"(r[2]),  "=r"(r[3]),
          "=r"(r[4]),  "=r"(r[5]),  "=r"(r[6]),  "=r"(r[7]),
          "=r"(r[8]),  "=r"(r[9]),  "=r"(r[10]), "=r"(r[11]),
          "=r"(r[12]), "=r"(r[13]), "=r"(r[14]), "=r"(r[15]),
          "=r"(r[16]), "=r"(r[17]), "=r"(r[18]), "=r"(r[19]),
          "=r"(r[20]), "=r"(r[21]), "=r"(r[22]), "=r"(r[23]),
          "=r"(r[24]), "=r"(r[25]), "=r"(r[26]), "=r"(r[27]),
          "=r"(r[28]), "=r"(r[29]), "=r"(r[30]), "=r"(r[31])
        : "r"(addr));
}
static constexpr uint64_t DESC_BASE =
    (2ull << 61) | (1ull << 46) | (64ull << 32) | (1ull << 16);
#define IDESC_F16 ((1u<<4)|((128u/8u)<<17)|((128u/16u)<<24))
#endif  // TC_PATH

#define NSTAGE 2
#define STAGE_BYTES 49152            /* A 16KB + B 32KB (fp16, K=64) */
#define SMEM_TOTAL (1024 + NSTAGE*STAGE_BYTES)   /* 99328 -> 2 CTAs/SM */

// ------------------------------------------------------------------
// k_fused: block-range dispatch of four independent prep jobs.
//   [0, 256)       : h0 copy+mask -> g_HW  FUSED with h_hat partials
//   [256, 4352)    : seqs fp16 copy -> g_SQ (8 floats/thr)
//   [4352, 8448)   : packed fp16 weight matrix g_WB
//   [8448, 8960)   : GEMV targets 2..9 (gw1, VV[0..6]) — input-only deps
// ------------------------------------------------------------------
__global__ void __launch_bounds__(256)
k_fused(const float* __restrict__ h0, const float* __restrict__ seqs,
        const float* __restrict__ Ww, const float* __restrict__ Wu,
        const float* __restrict__ Su, const float* __restrict__ Sw,
        const float* __restrict__ Sb, const float* __restrict__ Wv,
        const float* __restrict__ Wb, const int* __restrict__ seq_lens)
{
    const int bid = blockIdx.x;
    const int tid = threadIdx.x;
    __shared__ float sx1[4][512];

    if (bid < 256){
        // ---- h0 copy + mask + h_hat partials: one (b, sc) slab per block ----
        const int b  = bid & 31;
        const int sc = bid >> 5;           // 0..7
        const int len = seq_lens[b];
        const int s1 = sc*64;
        const int hc = tid*2;              // 2 consecutive h per thread
        const float* src = h0 + ((size_t)s1*32 + b)*512 + hc;
        __half* dst = g_HW + ((size_t)s1*32 + b)*512 + hc;
        float a0 = 0.f, a1 = 0.f;
        for (int s = s1; s < s1 + 64; ++s){
            float2 v = make_float2(0.f, 0.f);
            if (s < len) v = *(const float2*)src;
            *(__half2*)dst = __floats2half2_rn(v.x, v.y);
            a0 += v.x;
            a1 += v.y;
            src += 16384;
            dst += 16384;
        }
        g_HHATP[(size_t)sc*16384 + b*512 + hc]     = a0;
        g_HHATP[(size_t)sc*16384 + b*512 + hc + 1] = a1;
    } else if (bid < 4352){
        size_t idx = (size_t)(bid - 256) * 256 + tid;   // 8-float unit
        size_t e = idx << 3;
        float4 v0 = *(const float4*)(seqs + e);
        float4 v1 = *(const float4*)(seqs + e + 4);
        *(uint2*)(g_SQ + e)     = pack4h(v0);
        *(uint2*)(g_SQ + e + 4) = pack4h(v1);
    } else if (bid < 8448){
        int n = bid - 4352;
        __half* dst = g_WB + (size_t)n * KTOT;
        #pragma unroll
        for (int half = 0; half < 2; ++half){
            int k4 = tid*4 + half*1024;
            float4 v;
            if (n < 3584){
                int g = n >> 9, h = n & 511;
                int seg = k4 >> 9, kk = k4 & 511;
                const float* src = (seg < 3)
                    ? (Ww + ((size_t)(g*512 + h))*1536 + seg*512 + kk)
                    : (Wu + ((size_t)(g*512 + h))*512 + kk);
                v = *(const float4*)src;
            } else {
                int h = n - 3584;
                if (k4 < 512) v = *(const float4*)(Su + ((size_t)(512 + h))*512 + k4);
                else          v = make_float4(0.f,0.f,0.f,0.f);
            }
            *(uint2*)(dst + k4) = pack4h(v);
        }
    } else {
        // GEMV targets 2..9: 8 targets x 64 blocks each
        int idx = bid - 8448;            // 0..511
        const int target = 2 + (idx >> 6);
        int rest = idx & 63;
        const int bg = (rest >> 3) << 2; // 8 b-groups of 4
        const int hz = (rest & 7) << 6;  // 8 h-groups of 64

        for (int i = tid; i < 4*512; i += 256){
            int bb = i >> 9, k = i & 511;
            int b = bg + bb;
            sx1[bb][k] = h0[((size_t)(S_*Bb) + b)*Hh + k];
        }
        __syncthreads();

        const int warp = tid >> 5, lane = tid & 31;
        const int hh = hz + warp*8;

        float acc[4][8];
        #pragma unroll
        for (int bb=0;bb<4;bb++)
            #pragma unroll
            for (int j=0;j<8;j++) acc[bb][j] = 0.f;

        const float* wb1 = (target == 2)
            ? (Sw + ((size_t)(512 + hh))*512)
            : (Wv + ((size_t)((target-3)*512 + hh))*512);

        #pragma unroll 4
        for (int i = 0; i < 16; ++i){
            int k = lane + (i << 5);
            float w[8];
            #pragma unroll
            for (int j=0;j<8;j++) w[j] = wb1[(size_t)j*512 + k];
            #pragma unroll
            for (int bb=0;bb<4;bb++){
                float a = sx1[bb][k];
                #pragma unroll
                for (int j=0;j<8;j++) acc[bb][j] += a * w[j];
            }
        }

        #pragma unroll
        for (int bb=0;bb<4;bb++)
            #pragma unroll
            for (int j=0;j<8;j++){
                float v = acc[bb][j];
                #pragma unroll
                for (int o=16;o;o>>=1) v += __shfl_xor_sync(0xffffffffu, v, o);
                acc[bb][j] = v;
            }

        if (lane == 0){
            #pragma unroll
            for (int bb=0;bb<4;bb++){
                int b = bg + bb;
                #pragma unroll
                for (int j=0;j<8;j++){
                    int h = hh + j;
                    float v = acc[bb][j];
                    if (target == 2) g_GW1[b*512 + h] = v + Sb[512 + h];
                    else {
                        int g = target - 3;
                        g_VV[((size_t)g*Bb + b)*Hh + h] = v + Wb[g*512 + h];
                    }
                }
            }
        }
    }
}

// ------------------------------------------------------------------
// main GEMM (fp16 operands, fp32 accum). Tile M=128 x N=256.
// K-chunk = 64 fp16 (128B rows). grid(16,136), 2 CTAs/SM.
//   mb < 128 : GEMM tiles (R8-proven path)
//   mb >= 128: fg/og GEMV CTAs (fold of old k_small01; tail-scheduled)
// ------------------------------------------------------------------
__global__ void __launch_bounds__(256, 2)
k_gemm(const __grid_constant__ CUtensorMap mapHW,
       const __grid_constant__ CUtensorMap mapSQ,
       const __grid_constant__ CUtensorMap mapWB,
       const int* __restrict__ seq_lens,
       const float* __restrict__ h0,
       const float* __restrict__ Sw, const float* __restrict__ Su,
       const float* __restrict__ Sb)
{
    extern __shared__ char smem_raw[];
    const int tid = threadIdx.x;
    const int nb = blockIdx.x;     // 0..15
    const int mb = blockIdx.y;     // 0..135

    if (mb >= 128){
        // ---------------- fg/og GEMV (uses dynamic smem) ----------------
        int idx2 = (mb - 128)*16 + nb;     // 0..127
        const int target = idx2 >> 6;      // 0=fg, 1=og
        int rest = idx2 & 63;
        const int bg = (rest >> 3) << 2;
        const int hz = (rest & 7) << 6;
        float* sx1 = (float*)smem_raw;          // 4x512
        float* sx2 = sx1 + 4*512;               // 4x512

        for (int i = tid; i < 4*512; i += 256){
            int bb = i >> 9, k = i & 511;
            int b = bg + bb;
            sx1[bb*512 + k] = h0[((size_t)(S_*Bb) + b)*Hh + k];
            float s8 = 0.f;
            #pragma unroll
            for (int sc = 0; sc < 8; ++sc)
                s8 += g_HHATP[(size_t)sc*16384 + b*512 + k];
            sx2[bb*512 + k] = s8 * (1.0f/512.0f);
        }
        __syncthreads();

        const int warp = tid >> 5, lane = tid & 31;
        const int hh = hz + warp*8;
        const int si = (target==0) ? 0 : 2;

        float acc[4][8];
        #pragma unroll
        for (int bb=0;bb<4;bb++)
            #pragma unroll
            for (int j=0;j<8;j++) acc[bb][j] = 0.f;

        const float* wb1 = Sw + ((size_t)(si*512 + hh))*512;
        const float* wb2 = Su + ((size_t)(si*512 + hh))*512;

        #pragma unroll 4
        for (int i = 0; i < 16; ++i){
            int k = lane + (i << 5);
            float w1[8], w2[8];
            #pragma unroll
            for (int j=0;j<8;j++){ w1[j] = wb1[(size_t)j*512 + k]; w2[j] = wb2[(size_t)j*512 + k]; }
            #pragma unroll
            for (int bb=0;bb<4;bb++){
                float a1 = sx1[bb*512 + k];
                float a2 = sx2[bb*512 + k];
                #pragma unroll
                for (int j=0;j<8;j++) acc[bb][j] += a1*w1[j] + a2*w2[j];
            }
        }

        #pragma unroll
        for (int bb=0;bb<4;bb++)
            #pragma unroll
            for (int j=0;j<8;j++){
                float v = acc[bb][j];
                #pragma unroll
                for (int o=16;o;o>>=1) v += __shfl_xor_sync(0xffffffffu, v, o);
                acc[bb][j] = v;
            }

        if (lane == 0){
            #pragma unroll
            for (int bb=0;bb<4;bb++){
                int b = bg + bb;
                #pragma unroll
                for (int j=0;j<8;j++){
                    int h = hh + j;
                    float v = sigf(acc[bb][j] + Sb[si*512 + h]);
                    (target==0 ? g_FG : g_OG)[b*512 + h] = v;
                }
            }
        }
        return;
    }

    const int b  = mb >> 2;
    const int s0 = (mb & 3) << 7;
    if (s0 >= seq_lens[b]) return;

    const bool isFi = (nb >= 14);
    const int NC = isFi ? 8 : 32;

#if TC_PATH
    char* sbp = (char*)(((uintptr_t)smem_raw + 1023) & ~(uintptr_t)1023);
    const uint32_t sbu = smem_u32(sbp);
    const int warp = tid >> 5;

    if (tid == 0){
        #pragma unroll
        for (int s = 0; s < NSTAGE; ++s){
            mbar_init(sbu + 16 + 8*s, 1);     // full
            mbar_init(sbu + 48 + 8*s, 1);     // done
        }
        mbar_init(sbu + 80, 1);               // final
    }
    if (warp == 0){ tmem_alloc(sbu, 256); tmem_relinquish(); }
    __syncthreads();
    uint32_t tmem;
    asm volatile("ld.shared.b32 %0, [%1];" : "=r"(tmem) : "r"(sbu));

    if (warp == 0){
        if (elect_one()){
            for (int c = 0; c < NC; ++c){
                const int st = c % NSTAGE;
                const int q  = c / NSTAGE;
                if (c >= NSTAGE) mbar_wait(sbu + 48 + 8*st, (q - 1) & 1);
                const uint32_t full = sbu + 16 + 8*st;
                mbar_expect_tx(full, STAGE_BYTES);
                const uint32_t aAddr = sbu + 1024 + st*STAGE_BYTES;
                const uint32_t bAddr = aAddr + 16384;
                if (isFi){
                    tma_ld3(aAddr, &mapHW, c*64, b, s0, full);
                } else {
                    const int seg = c >> 3;
                    const int kc  = (c & 7) << 6;
                    if (seg < 3) tma_ld3(aAddr, &mapHW, kc, b, s0 + seg - 1, full);
                    else         tma_ld3(aAddr, &mapSQ, kc, b, s0, full);
                }
                tma_ld3(bAddr, &mapWB, c*64, nb*256, 0, full);
            }
        }
    } else if (warp == 1){
        if (elect_one()){
            for (int c = 0; c < NC; ++c){
                const int st = c % NSTAGE;
                const int q  = c / NSTAGE;
                mbar_wait(sbu + 16 + 8*st, q & 1);
                const uint32_t aAddr = sbu + 1024 + st*STAGE_BYTES;
                const uint32_t bAddr = aAddr + 16384;
                uint64_t ad  = DESC_BASE | ((aAddr >> 4) & 0x3FFFu);
                uint64_t bd0 = DESC_BASE | ((bAddr >> 4) & 0x3FFFu);
                uint64_t bd1 = bd0 + 1024;
                #pragma unroll
                for (int ks = 0; ks < 4; ++ks){
                    uint32_t en = (c > 0 || ks > 0) ? 1u : 0u;
                    mma_f16(tmem,       ad + 2*ks, bd0 + 2*ks, IDESC_F16, en);
                    mma_f16(tmem + 128, ad + 2*ks, bd1 + 2*ks, IDESC_F16, en);
                }
                mma_commit(sbu + 48 + 8*st);
            }
            mma_commit(sbu + 80);
        }
    }

    mbar_wait(sbu + 80, 0);
    tc_fence_after();

    // epilogue: TMEM f32 -> fp16 PRE
    {
        const int w = tid >> 5, lane = tid & 31;
        const int sub = w & 3;
        const int colh = (w >> 2) * 128;
        const uint32_t tb = tmem + ((uint32_t)sub << 21) + colh;
        __half* dst0 = g_PRE + ((size_t)(b*512 + s0 + sub*32 + lane))*NCOLS + nb*256 + colh;
        #pragma unroll
        for (int qq = 0; qq < 4; ++qq){
            uint32_t r[32];
            tmem_ld32(r, tb + qq*32);
            tmem_wait_ld();
            uint32_t hp[16];
            #pragma unroll
            for (int k = 0; k < 16; ++k){
                __half2 h2 = __floats2half2_rn(__uint_as_float(r[2*k]),
                                               __uint_as_float(r[2*k+1]));
                hp[k] = *(uint32_t*)&h2;
            }
            __half* dst = dst0 + qq*32;
            #pragma unroll
            for (int k = 0; k < 4; ++k)
                *(uint4*)(dst + k*8) = *(const uint4*)(hp + k*4);
        }
    }
    tc_fence_before();
    __syncthreads();
    if (warp == 0) tmem_dealloc(tmem, 256);

#else
    // ================= SIMT fallback (generic pass; not expected to run) =================
    float (*As)[132] = (float (*)[132])smem_raw;
    float (*Bs)[132] = (float (*)[132])(smem_raw + 16*132*4);

    const int arow = tid >> 2;
    const int acol = (tid & 3) << 2;
    const int m1 = arow, m2 = arow + 64;
    const int bcol = tid >> 2;
    const int bkg  = (tid & 3) << 2;
    const int ty8 = (tid >> 4) << 3;
    const int tx8 = (tid & 15) << 3;
    const int Kmax = isFi ? 512 : 2048;

    for (int p = 0; p < 2; ++p){
        const int coln = nb*256 + p*128;
        float acc[8][8];
        #pragma unroll
        for (int i=0;i<8;i++)
            #pragma unroll
            for (int j=0;j<8;j++) acc[i][j]=0.f;

        for (int k0 = 0; k0 < Kmax; k0 += 16){
            const int seg = isFi ? 1 : (k0 >> 9);
            const int kc  = isFi ? k0 : (k0 & 511);
            const int sh  = isFi ? 0 : (seg - 1);

            float4 a1, a2;
            if (!isFi && seg == 3){
                a1 = ld4h(g_SQ + ((size_t)((s0+m1)*32 + b))*512 + kc + acol);
                a2 = ld4h(g_SQ + ((size_t)((s0+m2)*32 + b))*512 + kc + acol);
            } else {
                int sp1 = s0 + m1 + sh, sp2 = s0 + m2 + sh;
                a1 = ((unsigned)sp1 < 512u) ? ld4h(g_HW + ((size_t)(sp1*32 + b))*512 + kc + acol)
                                            : make_float4(0.f,0.f,0.f,0.f);
                a2 = ((unsigned)sp2 < 512u) ? ld4h(g_HW + ((size_t)(sp2*32 + b))*512 + kc + acol)
                                            : make_float4(0.f,0.f,0.f,0.f);
            }
            float4 w1 = ld4h(g_WB + ((size_t)(coln + bcol))*KTOT + k0 + bkg);
            float4 w2 = ld4h(g_WB + ((size_t)(coln + bcol + 64))*KTOT + k0 + bkg);
            __syncthreads();
            As[acol+0][m1] = a1.x; As[acol+1][m1] = a1.y;
            As[acol+2][m1] = a1.z; As[acol+3][m1] = a1.w;
            As[acol+0][m2] = a2.x; As[acol+1][m2] = a2.y;
            As[acol+2][m2] = a2.z; As[acol+3][m2] = a2.w;
            Bs[bkg+0][bcol] = w1.x; Bs[bkg+1][bcol] = w1.y;
            Bs[bkg+2][bcol] = w1.z; Bs[bkg+3][bcol] = w1.w;
            Bs[bkg+0][bcol+64] = w2.x; Bs[bkg+1][bcol+64] = w2.y;
            Bs[bkg+2][bcol+64] = w2.z; Bs[bkg+3][bcol+64] = w2.w;
            __syncthreads();
            #pragma unroll
            for (int kk = 0; kk < 16; ++kk){
                float a[8], bv[8];
                *(float4*)&a[0]  = *(const float4*)&As[kk][ty8];
                *(float4*)&a[4]  = *(const float4*)&As[kk][ty8+4];
                *(float4*)&bv[0] = *(const float4*)&Bs[kk][tx8];
                *(float4*)&bv[4] = *(const float4*)&Bs[kk][tx8+4];
                #pragma unroll
                for (int i=0;i<8;i++)
                    #pragma unroll
                    for (int j=0;j<8;j++)
                        acc[i][j] += a[i]*bv[j];
            }
        }
        #pragma unroll
        for (int i=0;i<8;i++){
            __half* pp = g_PRE + ((size_t)(b*512 + s0 + ty8 + i))*NCOLS + coln + tx8;
            *(uint2*)pp     = pack4h(make_float4(acc[i][0],acc[i][1],acc[i][2],acc[i][3]));
            *(uint2*)(pp+4) = pack4h(make_float4(acc[i][4],acc[i][5],acc[i][6],acc[i][7]));
        }
        __syncthreads();
    }
#endif
}

// ------------------------------------------------------------------
// global cell, stage 1: partial (l, cacc) over 8-s chunks
// ------------------------------------------------------------------
__global__ void kg_part(const float* __restrict__ c0, const int* __restrict__ seq_lens)
{
    int b = blockIdx.x, sc = blockIdx.y, h = threadIdx.x;
    int len = seq_lens[b];
    int s1 = sc*8;
    int s2 = min(s1 + 8, len);
    float g1 = g_GW1[b*512 + h];
    const __half* prep = g_PRE + ((size_t)(b*512 + s1))*NCOLS + 3584 + h;
    const float* cp    = c0 + ((size_t)s1*32 + b)*512 + h;
    float l = 0.f, cacc = 0.f;
    for (int s = s1; s < s2; ++s){
        float e = __expf(sigf(g1 + __half2float(*prep)));
        l += e;
        cacc += e * (*cp);
        prep += NCOLS;
        cp   += 16384;
    }
    g_GPl[(size_t)sc*16384 + b*512 + h] = l;
    g_GPc[(size_t)sc*16384 + b*512 + h] = cacc;
}

// ------------------------------------------------------------------
// k_tail: window-cell epilogue + global-cell final (tail-appended).
//   [0, 8192)     : k_epi work (4 h per thread)
//   [8192, 8448)  : kg_fin work (quarter-split coalesced reduce)
// Launched after kg_part, so both dependencies are satisfied.
// ------------------------------------------------------------------
__global__ void __launch_bounds__(256)
k_tail(const float* __restrict__ c0, const int* __restrict__ seq_lens,
       float* __restrict__ out)
{
    __shared__ float sl[256], sc_[256];
    const int bid = blockIdx.x;
    const int tid = threadIdx.x;
    const size_t CT = (size_t)(S_+1)*Bb*Hh;

    if (bid < 8192){
        // ---------------- window cell epilogue ----------------
        size_t idx = (size_t)bid*256 + tid;   // 4h unit index
        int h4 = (int)(idx & 127);
        size_t rc = idx >> 7;          // s*32 + b
        int b = (int)(rc & 31);
        int s = (int)(rc >> 5);
        int len = seq_lens[b];
        float4* o1 = (float4*)(out + rc*512 + h4*4);
        float4* o2 = (float4*)(out + CT + rc*512 + h4*4);
        if (s >= len){
            *o1 = make_float4(0.f, 0.f, 0.f, 0.f);
            *o2 = make_float4(0.f, 0.f, 0.f, 0.f);
            return;
        }

        const __half* prow = g_PRE + ((size_t)b*512 + s)*NCOLS + h4*4;
        float px[7][4];
        #pragma unroll
        for (int g = 0; g < 7; ++g){
            uint2 raw = *(const uint2*)(prow + g*512);
            __half2 a = *(__half2*)&raw.x;
            __half2 bb2 = *(__half2*)&raw.y;
            float4 vv = *(const float4*)(g_VV + ((size_t)g*Bb + b)*Hh + h4*4);
            px[g][0] = __low2float(a)   + vv.x;
            px[g][1] = __high2float(a)  + vv.y;
            px[g][2] = __low2float(bb2) + vv.z;
            px[g][3] = __high2float(bb2)+ vv.w;
        }

        float4 cl  = (s >= 1) ? *(const float4*)(c0 + (rc-32)*Hh + h4*4) : make_float4(0.f,0.f,0.f,0.f);
        float4 cc  = *(const float4*)(c0 + rc*Hh + h4*4);
        float4 cr  = (s+1 < S_ && s+1 < len) ? *(const float4*)(c0 + (rc+32)*Hh + h4*4)
                                             : make_float4(0.f,0.f,0.f,0.f);
        float4 cg1 = *(const float4*)(c0 + ((size_t)(S_*Bb) + b)*Hh + h4*4);

        float clv[4] = {cl.x, cl.y, cl.z, cl.w};
        float ccv[4] = {cc.x, cc.y, cc.z, cc.w};
        float crv[4] = {cr.x, cr.y, cr.z, cr.w};
        float cgv[4] = {cg1.x, cg1.y, cg1.z, cg1.w};
        float hw[4], cw4[4];
        #pragma unroll
        for (int j = 0; j < 4; ++j){
            float si_ = sigf(px[0][j]);
            float sl_ = sigf(px[1][j]);
            float sr_ = sigf(px[2][j]);
            float sf_ = sigf(px[3][j]);
            float ss_ = sigf(px[4][j]);
            float so_ = sigf(px[5][j]);
            float u_  = tanhf(px[6][j]);

            float e0 = __expf(sl_);
            float e1 = __expf(sf_);
            float e2 = __expf(sr_);
            float e3 = __expf(ss_);
            float e4 = __expf(si_);
            float inv = 1.f/(e0+e1+e2+e3+e4);

            float cw = (e0*clv[j] + e1*ccv[j] + e2*crv[j] + e3*cgv[j] + e4*u_) * inv;
            hw[j] = so_ * tanhf(cw);
            cw4[j] = cw;
        }
        *o1 = make_float4(hw[0], hw[1], hw[2], hw[3]);
        *o2 = make_float4(cw4[0], cw4[1], cw4[2], cw4[3]);
    } else {
        // ---------------- global cell final reduce ----------------
        const int e = (bid - 8192)*64 + (tid & 63);  // element in [0,16384)
        const int q = tid >> 6;                      // quarter 0..3
        float l = 0.f, cacc = 0.f;
        #pragma unroll
        for (int i = 0; i < 16; ++i){
            int sc = q*16 + i;
            l    += g_GPl[(size_t)sc*16384 + e];
            cacc += g_GPc[(size_t)sc*16384 + e];
        }
        sl[tid] = l; sc_[tid] = cacc;
        __syncthreads();
        if (tid < 64){
            l    = sl[tid]  + sl[tid+64]  + sl[tid+128]  + sl[tid+192];
            cacc = sc_[tid] + sc_[tid+64] + sc_[tid+128] + sc_[tid+192];
            int b = e >> 9;
            int h = e & 511;
            size_t gidx = ((size_t)(S_*Bb) + b)*Hh + h;
            float cg = g_FG[b*512 + h]*c0[gidx] + cacc / l;
            float hg = g_OG[b*512 + h]*tanhf(cg);
            out[gidx] = hg;
            out[CT + gidx] = cg;
        }
    }
}

// ------------------------------------------------------------------
// host
// ------------------------------------------------------------------
typedef CUresult (*EncFn)(CUtensorMap*, CUtensorMapDataType, cuuint32_t, void*,
                          const cuuint64_t*, const cuuint64_t*,
                          const cuuint32_t*, const cuuint32_t*,
                          CUtensorMapInterleave, CUtensorMapSwizzle,
                          CUtensorMapL2promotion, CUtensorMapFloatOOBfill);

static void make_map3h(EncFn enc, CUtensorMap* m, void* ptr,
                       uint64_t d0, uint64_t d1, uint64_t d2,
                       uint64_t str1B, uint64_t str2B,
                       uint32_t b0, uint32_t b1, uint32_t b2)
{
    cuuint64_t dims[3] = {d0, d1, d2};
    cuuint64_t strides[2] = {str1B, str2B};
    cuuint32_t box[3] = {b0, b1, b2};
    cuuint32_t es[3] = {1, 1, 1};
    enc(m, CU_TENSOR_MAP_DATA_TYPE_FLOAT16, 3, ptr, dims, strides, box, es,
        CU_TENSOR_MAP_INTERLEAVE_NONE, CU_TENSOR_MAP_SWIZZLE_128B,
        CU_TENSOR_MAP_L2_PROMOTION_L2_128B, CU_TENSOR_MAP_FLOAT_OOB_FILL_NONE);
}

extern "C" void kernel_launch(void* const* d_in, const int* in_sizes, int n_in,
                              void* d_out, int out_size)
{
    const float* seqs     = (const float*)d_in[0];
    const int*   seq_lens = (const int*)  d_in[1];
    const float* h0       = (const float*)d_in[2];
    const float* c0       = (const float*)d_in[3];
    const float* Ww       = (const float*)d_in[4];
    const float* Wu       = (const float*)d_in[5];
    const float* Wv       = (const float*)d_in[6];
    const float* Wb       = (const float*)d_in[7];
    const float* Sw       = (const float*)d_in[8];
    const float* Su       = (const float*)d_in[9];
    const float* Sb       = (const float*)d_in[10];
    float* out = (float*)d_out;

    static EncFn enc = nullptr;
    static CUtensorMap mapHW, mapSQ, mapWB;
    static bool maps_ready = false;
    if (!maps_ready){
        cudaDriverEntryPointQueryResult qr;
        void* fn = nullptr;
        cudaGetDriverEntryPoint("cuTensorMapEncodeTiled", &fn, cudaEnableDefault, &qr);
        enc = (EncFn)fn;
        void *pHW = nullptr, *pSQ = nullptr, *pWB = nullptr;
        cudaGetSymbolAddress(&pHW, g_HW);
        cudaGetSymbolAddress(&pSQ, g_SQ);
        cudaGetSymbolAddress(&pWB, g_WB);
        // A views: (h=512, b=32, s=512) fp16; box (64,1,128)
        make_map3h(enc, &mapHW, pHW, 512, 32, 512, 512*2, 32*512*2, 64, 1, 128);
        make_map3h(enc, &mapSQ, pSQ, 512, 32, 512, 512*2, 32*512*2, 64, 1, 128);
        // B view: (k=2048, n=4096, 1) fp16; box (64,256,1)
        make_map3h(enc, &mapWB, pWB, 2048, 4096, 1,
                   (uint64_t)2048*2, (uint64_t)2048*4096*2, 64, 256, 1);
        cudaFuncSetAttribute(k_gemm, cudaFuncAttributeMaxDynamicSharedMemorySize, SMEM_TOTAL);
        maps_ready = true;
    }

    k_fused <<<8960, 256>>>(h0, seqs, Ww, Wu, Su, Sw, Sb, Wv, Wb, seq_lens);
    k_gemm  <<<dim3(16, 136), 256, SMEM_TOTAL>>>(mapHW, mapSQ, mapWB, seq_lens,
                                                 h0, Sw, Su, Sb);
    kg_part <<<dim3(32, 64), 512>>>(c0, seq_lens);
    k_tail  <<<8448, 256>>>(c0, seq_lens, out);
}